// round 4
// baseline (speedup 1.0000x reference)
#include <cuda_runtime.h>
#include <math.h>

#define BS   512
#define NROW 512
// smem: buf0(8192 c) + buf1(8192 c) + Fc(4097 c) + TW(4097 c) + Ft(8194 f) + red(32 f)
#define SMEM_BYTES (24578*8 + 8226*4)

__device__ float g_sigma[NROW];

__device__ __forceinline__ int SW(int i) { return i ^ ((i >> 5) & 31); }

__device__ __forceinline__ float2 cmul(float2 a, float2 b) {
    return make_float2(a.x*b.x - a.y*b.y, a.x*b.y + a.y*b.x);
}

// 4-point DFT in registers. Y_j = sum_r x_r * exp(DIR*2pi*i*j*r/4).
template<int DIR>
__device__ __forceinline__ void dft4i(float2& a, float2& b, float2& c, float2& d) {
    float2 apc = make_float2(a.x + c.x, a.y + c.y);
    float2 amc = make_float2(a.x - c.x, a.y - c.y);
    float2 bpd = make_float2(b.x + d.x, b.y + d.y);
    float2 bmd = make_float2(b.x - d.x, b.y - d.y);
    float2 jb;   // DIR * i * bmd
    if (DIR > 0) jb = make_float2(-bmd.y,  bmd.x);
    else         jb = make_float2( bmd.y, -bmd.x);
    a = make_float2(apc.x + bpd.x, apc.y + bpd.y);
    b = make_float2(amc.x + jb.x,  amc.y + jb.y);
    c = make_float2(apc.x - bpd.x, apc.y - bpd.y);
    d = make_float2(amc.x - jb.x,  amc.y - jb.y);
}

// Internal W16 twiddles for the 16-pt DFT: v[b+4c] *= exp(DIR*2pi*i*b*c/16)
template<int DIR>
__device__ __forceinline__ void applyW16(float2* v) {
    const float C1 = 0.9238795325112867f, S1 = 0.3826834323650898f;
    const float H  = 0.7071067811865476f;
    const float D  = (DIR > 0) ? 1.0f : -1.0f;
    v[5]  = cmul(v[5],  make_float2( C1,  D*S1));   // t=1
    v[9]  = cmul(v[9],  make_float2(  H,  D*H));    // t=2
    v[13] = cmul(v[13], make_float2( S1,  D*C1));   // t=3
    v[6]  = cmul(v[6],  make_float2(  H,  D*H));    // t=2
    v[10] = cmul(v[10], make_float2(0.f,  D*1.f));  // t=4
    v[14] = cmul(v[14], make_float2( -H,  D*H));    // t=6
    v[7]  = cmul(v[7],  make_float2( S1,  D*C1));   // t=3
    v[11] = cmul(v[11], make_float2( -H,  D*H));    // t=6
    v[15] = cmul(v[15], make_float2(-C1, -D*S1));   // t=9
}

// One radix-16 Stockham round. Gathers x[ib + r*off] (r=0..15), 16-pt DFT in
// registers, applies W_ln^{j*p}, scatters y[ob + j*s].
// off = m*s = S/16 (constant per FFT size). If ZHI, inputs r>=8 are zero
// (fused zero-padding; only valid for the s=1 round of the 8192 FFT).
template<int DIR, bool ZHI>
__device__ __forceinline__ void r16_round(const float2* __restrict__ x,
                                          float2* __restrict__ y,
                                          int lgln, int ls,
                                          const float2* __restrict__ TW,
                                          int nbf, int off)
{
    const int s = 1 << ls;
    for (int id = threadIdx.x; id < nbf; id += BS) {
        const int q  = id & (s - 1);
        const int p  = id >> ls;
        const int ib = q + (p << ls);
        float2 v[16];
        #pragma unroll
        for (int r = 0; r < 16; r++) {
            if (ZHI && r >= 8) v[r] = make_float2(0.f, 0.f);
            else               v[r] = x[SW(ib + r * off)];
        }
        // step 1: DFT4 over a for each b  (x_{4a+b} -> A_b(c) at v[b+4c])
        #pragma unroll
        for (int bb = 0; bb < 4; bb++)
            dft4i<DIR>(v[bb], v[bb+4], v[bb+8], v[bb+12]);
        applyW16<DIR>(v);
        // step 2: DFT4 over b within each group of 4 (X_{c+4d} at v[4c+d])
        #pragma unroll
        for (int c = 0; c < 4; c++)
            dft4i<DIR>(v[4*c], v[4*c+1], v[4*c+2], v[4*c+3]);
        // stage twiddle W_ln^{j*p} and scatter (j = c + 4d <-> slot v[4c+d])
        float2 t  = TW[p << (14 - lgln)];
        float2 w1 = make_float2(t.x, (DIR > 0) ? t.y : -t.y);
        float2 w2 = cmul(w1, w1);
        float2 w3 = cmul(w2, w1);
        float2 w4 = cmul(w2, w2);
        const int ob = q + ((p << 4) << ls);
        y[SW(ob)]         = v[0];
        y[SW(ob + s)]     = cmul(w1, v[4]);
        y[SW(ob + 2*s)]   = cmul(w2, v[8]);
        y[SW(ob + 3*s)]   = cmul(w3, v[12]);
        float2 wr = w4;
        #pragma unroll
        for (int d = 1; d < 4; d++) {
            const int jb = 4 * d;
            y[SW(ob + (jb    )*s)] = cmul(wr, v[d]);
            y[SW(ob + (jb + 1)*s)] = cmul(cmul(wr, w1), v[4 + d]);
            y[SW(ob + (jb + 2)*s)] = cmul(cmul(wr, w2), v[8 + d]);
            y[SW(ob + (jb + 3)*s)] = cmul(cmul(wr, w3), v[12 + d]);
            if (d < 3) wr = cmul(wr, w4);
        }
    }
}

// Final twiddle-free radix-2 round for the 8192 FFT (s = 4096).
__device__ __forceinline__ void r2_round(const float2* __restrict__ x,
                                         float2* __restrict__ y, bool half)
{
    for (int id = threadIdx.x; id < 4096; id += BS) {
        float2 a = x[SW(id)], b = x[SW(id + 4096)];
        y[SW(id)] = make_float2(a.x + b.x, a.y + b.y);
        if (!half) y[SW(id + 4096)] = make_float2(a.x - b.x, a.y - b.y);
    }
}

// 4096-pt complex FFT: 3 radix-16 rounds. Input x, result lands in y.
template<int DIR>
__device__ void cfft4096(float2* x, float2* y, const float2* TW)
{
    r16_round<DIR,false>(x, y, 12, 0, TW, 256, 256); __syncthreads();
    r16_round<DIR,false>(y, x,  8, 4, TW, 256, 256); __syncthreads();
    r16_round<DIR,false>(x, y,  4, 8, TW, 256, 256); __syncthreads();
}

// 8192-pt complex FFT: 3 radix-16 rounds + final radix-2. Result lands in x.
// ZHI: treat x[4096..8191] as zero in round 1. half_last: only store the
// lower 4096 outputs of the final round.
template<int DIR, bool ZHI>
__device__ void cfft8192(float2* x, float2* y, const float2* TW, bool half_last)
{
    r16_round<DIR,ZHI  >(x, y, 13, 0, TW, 512, 512); __syncthreads();
    r16_round<DIR,false>(y, x,  9, 4, TW, 512, 512); __syncthreads();
    r16_round<DIR,false>(x, y,  5, 8, TW, 512, 512); __syncthreads();
    r2_round(y, x, half_last);                        __syncthreads();
}

// Real-FFT unpack: Bk = V[k], Bkk = V[Nh-k] from packed transform Z.
__device__ __forceinline__ void unpack_pair(float2 Zk, float2 Zkk, float2 W,
                                            float2& Bk, float2& Bkk)
{
    float2 Ze  = make_float2(0.5f*(Zk.x + Zkk.x), 0.5f*(Zk.y - Zkk.y));
    float2 Zo  = make_float2(0.5f*(Zk.y + Zkk.y), -0.5f*(Zk.x - Zkk.x));
    float2 WZo = cmul(W, Zo);
    Bk  = make_float2(Ze.x + WZo.x, Ze.y + WZo.y);
    Bkk = make_float2(Ze.x - WZo.x, WZo.y - Ze.y);
}

__device__ __forceinline__ void repack_pair(float2 Uk, float2 Ukk, float2 W,
                                            float2& zk, float2& zkk)
{
    float2 Eu = make_float2(0.5f*(Uk.x + Ukk.x), 0.5f*(Uk.y - Ukk.y));
    float2 D  = make_float2(0.5f*(Uk.x - Ukk.x), 0.5f*(Uk.y + Ukk.y));
    float2 Wc = make_float2(W.x, -W.y);
    float2 Ou = cmul(D, Wc);
    zk  = make_float2(Eu.x - Ou.y, Eu.y + Ou.x);
    zkk = make_float2(Eu.x + Ou.y, Ou.x - Eu.y);
}

__device__ float block_reduce_sum(float v, float* red)
{
    __syncthreads();
    #pragma unroll
    for (int o = 16; o; o >>= 1) v += __shfl_down_sync(0xffffffffu, v, o);
    if ((threadIdx.x & 31) == 0) red[threadIdx.x >> 5] = v;
    __syncthreads();
    if (threadIdx.x < 32) {
        float t = (threadIdx.x < 16) ? red[threadIdx.x] : 0.0f;
        #pragma unroll
        for (int o = 8; o; o >>= 1) t += __shfl_down_sync(0xffffffffu, t, o);
        if (threadIdx.x == 0) red[0] = t;
    }
    __syncthreads();
    return red[0];
}

// Fused unpack * Fc * repack, in place on Z[0..4095] (Nh=4096, N=8192).
__device__ __forceinline__ void specA(float2* Z, const float2* __restrict__ Fc,
                                      const float2* __restrict__ TW)
{
    for (int k = threadIdx.x; k <= 2048; k += BS) {
        const int kk = (4096 - k) & 4095;
        float2 t = TW[k << 1];
        float2 W = make_float2(t.x, -t.y);
        float2 Bk, Bkk;
        unpack_pair(Z[SW(k)], Z[SW(kk)], W, Bk, Bkk);
        float2 Uk  = cmul(Bk,  Fc[k]);
        float2 Ukk = cmul(Bkk, Fc[4096 - k]);
        float2 zk, zkk;
        repack_pair(Uk, Ukk, W, zk, zkk);
        Z[SW(k)] = zk;
        if (k != 0) Z[SW(kk)] = zkk;
    }
}

// Fused unpack * Ft(real) * repack, in place on Z[0..8191] (Nh=8192, N=16384).
__device__ __forceinline__ void specB(float2* Z, const float* __restrict__ Ft,
                                      const float2* __restrict__ TW)
{
    for (int k = threadIdx.x; k <= 4096; k += BS) {
        const int kk = (8192 - k) & 8191;
        float2 t = TW[k];
        float2 W = make_float2(t.x, -t.y);
        float2 Bk, Bkk;
        unpack_pair(Z[SW(k)], Z[SW(kk)], W, Bk, Bkk);
        const float fk  = Ft[k];
        const float fkk = Ft[8192 - k];
        float2 Uk  = make_float2(Bk.x * fk,  Bk.y * fk);
        float2 Ukk = make_float2(Bkk.x * fkk, Bkk.y * fkk);
        float2 zk, zkk;
        repack_pair(Uk, Ukk, W, zk, zkk);
        Z[SW(k)] = zk;
        if (k != 0) Z[SW(kk)] = zkk;
    }
}

__global__ void __launch_bounds__(BS)
power_kernel(const float* __restrict__ gx, const float* __restrict__ gc,
             const float* __restrict__ gb0)
{
    extern __shared__ float2 smem2[];
    float2* buf0 = smem2;               // 8192
    float2* buf1 = smem2 + 8192;        // 8192
    float2* Fc   = smem2 + 16384;       // 4097
    float2* TW   = smem2 + 20481;       // 4097 : (cos,sin)(2*pi*r/16384)
    float*  Ft   = (float*)(smem2 + 24578); // 8194
    float*  red  = Ft + 8194;           // 32

    const int tid = threadIdx.x;
    const int row = blockIdx.x;
    const float* xr = gx  + (size_t)row * 8192;
    const float* cr = gc  + (size_t)row * 8192;
    const float* br = gb0 + (size_t)row * 8192;

    // ---- twiddle table ----
    for (int r = tid; r <= 4096; r += BS) {
        float sv, cv;
        sincospif((float)r * (1.0f / 8192.0f), &sv, &cv);
        TW[r] = make_float2(cv, sv);
    }
    __syncthreads();

    // ---- Fc = DFT_8192(circ) / 4096 (half spectrum) ----
    for (int n = tid; n < 4096; n += BS)
        buf0[SW(n)] = make_float2(cr[2*n], cr[2*n + 1]);
    __syncthreads();
    cfft4096<-1>(buf0, buf1, TW);                 // result in buf1
    {
        float2* Z = buf1;
        const float sc = 1.0f / 4096.0f;
        for (int k = tid; k <= 2048; k += BS) {
            const int kk = (4096 - k) & 4095;
            float2 t = TW[k << 1];
            float2 W = make_float2(t.x, -t.y);
            float2 Bk, Bkk;
            unpack_pair(Z[SW(k)], Z[SW(kk)], W, Bk, Bkk);
            Fc[k]        = make_float2(Bk.x * sc,  Bk.y * sc);
            Fc[4096 - k] = make_float2(Bkk.x * sc, Bkk.y * sc);
        }
    }
    __syncthreads();

    // ---- Ft = Re(DFT_16384([x, 0, flip(x[1:])])) / 8192 (real half spectrum) ----
    for (int n = tid; n < 8192; n += BS) {
        const int j0 = 2*n, j1 = 2*n + 1;
        float e0 = (j0 < 8192) ? xr[j0] : ((j0 == 8192) ? 0.0f : xr[16384 - j0]);
        float e1 = (j1 < 8192) ? xr[j1] : xr[16384 - j1];
        buf0[SW(n)] = make_float2(e0, e1);
    }
    __syncthreads();
    cfft8192<-1,false>(buf0, buf1, TW, false);    // result in buf0
    {
        float2* Z = buf0;
        const float sc = 1.0f / 8192.0f;
        for (int k = tid; k <= 4096; k += BS) {
            const int kk = (8192 - k) & 8191;
            float2 t = TW[k];
            float2 W = make_float2(t.x, -t.y);
            float2 Bk, Bkk;
            unpack_pair(Z[SW(k)], Z[SW(kk)], W, Bk, Bkk);
            Ft[k]        = Bk.x * sc;
            Ft[8192 - k] = Bkk.x * sc;
        }
    }
    __syncthreads();

    // ---- b = b0 / ||b0||, thread t owns b[16t .. 16t+15] ----
    float b[16];
    {
        #pragma unroll
        for (int q4 = 0; q4 < 4; q4++) {
            const float4 v = *(const float4*)(br + tid*16 + q4*4);
            b[q4*4+0] = v.x; b[q4*4+1] = v.y; b[q4*4+2] = v.z; b[q4*4+3] = v.w;
        }
        float ss = 0.0f;
        #pragma unroll
        for (int i = 0; i < 16; i++) ss += b[i]*b[i];
        float tot = block_reduce_sum(ss, red);
        float inv = 1.0f / sqrtf(tot);
        #pragma unroll
        for (int i = 0; i < 16; i++) b[i] *= inv;
    }

    // ---- 100 power iterations + 1 final application ----
    for (int it = 0; it <= 100; ++it) {
        // pack b: buf0[n] = (b[2n], b[2n+1]), n = 8*tid + j
        #pragma unroll
        for (int j = 0; j < 8; ++j)
            buf0[SW(8*tid + j)] = make_float2(b[2*j], b[2*j + 1]);
        __syncthreads();

        // u = IFFT( Fc * FFT(b) )   (8192-pt real conv via 4096-pt CFFT)
        cfft4096<-1>(buf0, buf1, TW);             // -> buf1
        specA(buf1, Fc, TW);
        __syncthreads();
        cfft4096<+1>(buf1, buf0, TW);             // -> buf0 : packed u

        // w = first 8192 of IFFT_16384( Ft * FFT_16384([u,0]) )
        cfft8192<-1,true >(buf0, buf1, TW, false); // zero-pad fused; -> buf0
        specB(buf0, Ft, TW);
        __syncthreads();
        cfft8192<+1,false>(buf0, buf1, TW, true);  // lower half only; -> buf0

        float w_[16];
        #pragma unroll
        for (int j = 0; j < 8; ++j) {
            float2 v = buf0[SW(8*tid + j)];
            w_[2*j]     = v.x;
            w_[2*j + 1] = v.y;
        }

        if (it < 100) {
            float nb[16];
            float ss = 0.0f;
            #pragma unroll
            for (int i = 0; i < 16; i++) { nb[i] = b[i] - w_[i]; ss += nb[i]*nb[i]; }
            float tot = block_reduce_sum(ss, red);
            float inv = 1.0f / sqrtf(tot);
            #pragma unroll
            for (int i = 0; i < 16; i++) b[i] = nb[i] * inv;
        } else {
            float dp = 0.0f;
            #pragma unroll
            for (int i = 0; i < 16; i++) dp += b[i] * w_[i];
            float tot = block_reduce_sum(dp, red);
            if (tid == 0) g_sigma[row] = 1.0f - tot;   // sigma = b.(b-w) = 1 - b.w
        }
    }
}

__global__ void finalize_kernel(float* __restrict__ out)
{
    __shared__ float red[16];
    const int t = threadIdx.x;   // 512 threads
    float v = fabsf(g_sigma[t]);
    #pragma unroll
    for (int o = 16; o; o >>= 1) v += __shfl_down_sync(0xffffffffu, v, o);
    if ((t & 31) == 0) red[t >> 5] = v;
    __syncthreads();
    if (t < 16) {
        float s = red[t];
        #pragma unroll
        for (int o = 8; o; o >>= 1) s += __shfl_down_sync(0xffffu, s, o);
        if (t == 0) out[0] = s * (1.0f / 512.0f);
    }
}

extern "C" void kernel_launch(void* const* d_in, const int* in_sizes, int n_in,
                              void* d_out, int out_size)
{
    (void)in_sizes; (void)n_in; (void)out_size;
    const float* x    = (const float*)d_in[0];
    const float* circ = (const float*)d_in[1];
    const float* b0   = (const float*)d_in[2];

    cudaFuncSetAttribute(power_kernel,
                         cudaFuncAttributeMaxDynamicSharedMemorySize, SMEM_BYTES);
    power_kernel<<<NROW, BS, SMEM_BYTES>>>(x, circ, b0);
    finalize_kernel<<<1, 512>>>((float*)d_out);
}

// round 5
// speedup vs baseline: 1.0001x; 1.0001x over previous
#include <cuda_runtime.h>
#include <math.h>

#define BS   512
#define NROW 512
// smem: buf0(8192 c) + buf1(8192 c) + Fc(4097 c) + TW(4097 c) + Ft(8194 f) + red(32 f)
#define SMEM_BYTES (24578*8 + 8226*4)

__device__ float g_sigma[NROW];

__device__ __forceinline__ int SW(int i) { return i ^ ((i >> 5) & 31); }

__device__ __forceinline__ float2 cmul(float2 a, float2 b) {
    return make_float2(a.x*b.x - a.y*b.y, a.x*b.y + a.y*b.x);
}

// 4-point DFT in registers. Y_j = sum_r x_r * exp(DIR*2pi*i*j*r/4).
template<int DIR>
__device__ __forceinline__ void dft4i(float2& a, float2& b, float2& c, float2& d) {
    float2 apc = make_float2(a.x + c.x, a.y + c.y);
    float2 amc = make_float2(a.x - c.x, a.y - c.y);
    float2 bpd = make_float2(b.x + d.x, b.y + d.y);
    float2 bmd = make_float2(b.x - d.x, b.y - d.y);
    float2 jb;   // DIR * i * bmd
    if (DIR > 0) jb = make_float2(-bmd.y,  bmd.x);
    else         jb = make_float2( bmd.y, -bmd.x);
    a = make_float2(apc.x + bpd.x, apc.y + bpd.y);
    b = make_float2(amc.x + jb.x,  amc.y + jb.y);
    c = make_float2(apc.x - bpd.x, apc.y - bpd.y);
    d = make_float2(amc.x - jb.x,  amc.y - jb.y);
}

// Internal W16 twiddles for the 16-pt DFT: v[b+4c] *= exp(DIR*2pi*i*b*c/16)
template<int DIR>
__device__ __forceinline__ void applyW16(float2* v) {
    const float C1 = 0.9238795325112867f, S1 = 0.3826834323650898f;
    const float H  = 0.7071067811865476f;
    const float D  = (DIR > 0) ? 1.0f : -1.0f;
    v[5]  = cmul(v[5],  make_float2( C1,  D*S1));   // t=1
    v[9]  = cmul(v[9],  make_float2(  H,  D*H));    // t=2
    v[13] = cmul(v[13], make_float2( S1,  D*C1));   // t=3
    v[6]  = cmul(v[6],  make_float2(  H,  D*H));    // t=2
    v[10] = cmul(v[10], make_float2(0.f,  D*1.f));  // t=4
    v[14] = cmul(v[14], make_float2( -H,  D*H));    // t=6
    v[7]  = cmul(v[7],  make_float2( S1,  D*C1));   // t=3
    v[11] = cmul(v[11], make_float2( -H,  D*H));    // t=6
    v[15] = cmul(v[15], make_float2(-C1, -D*S1));   // t=9
}

// One radix-16 Stockham round. Gathers x[ib + r*off] (r=0..15), 16-pt DFT in
// registers, applies W_ln^{j*p}, scatters y[ob + j*s].
// off = m*s = S/16 (constant per FFT size). If ZHI, inputs r>=8 are zero
// (fused zero-padding; only valid for the s=1 round of the 8192 FFT).
template<int DIR, bool ZHI>
__device__ __forceinline__ void r16_round(const float2* __restrict__ x,
                                          float2* __restrict__ y,
                                          int lgln, int ls,
                                          const float2* __restrict__ TW,
                                          int nbf, int off)
{
    const int s = 1 << ls;
    for (int id = threadIdx.x; id < nbf; id += BS) {
        const int q  = id & (s - 1);
        const int p  = id >> ls;
        const int ib = q + (p << ls);
        float2 v[16];
        #pragma unroll
        for (int r = 0; r < 16; r++) {
            if (ZHI && r >= 8) v[r] = make_float2(0.f, 0.f);
            else               v[r] = x[SW(ib + r * off)];
        }
        // step 1: DFT4 over a for each b  (x_{4a+b} -> A_b(c) at v[b+4c])
        #pragma unroll
        for (int bb = 0; bb < 4; bb++)
            dft4i<DIR>(v[bb], v[bb+4], v[bb+8], v[bb+12]);
        applyW16<DIR>(v);
        // step 2: DFT4 over b within each group of 4 (X_{c+4d} at v[4c+d])
        #pragma unroll
        for (int c = 0; c < 4; c++)
            dft4i<DIR>(v[4*c], v[4*c+1], v[4*c+2], v[4*c+3]);
        // stage twiddle W_ln^{j*p} and scatter (j = c + 4d <-> slot v[4c+d])
        float2 t  = TW[p << (14 - lgln)];
        float2 w1 = make_float2(t.x, (DIR > 0) ? t.y : -t.y);
        float2 w2 = cmul(w1, w1);
        float2 w3 = cmul(w2, w1);
        float2 w4 = cmul(w2, w2);
        const int ob = q + ((p << 4) << ls);
        y[SW(ob)]         = v[0];
        y[SW(ob + s)]     = cmul(w1, v[4]);
        y[SW(ob + 2*s)]   = cmul(w2, v[8]);
        y[SW(ob + 3*s)]   = cmul(w3, v[12]);
        float2 wr = w4;
        #pragma unroll
        for (int d = 1; d < 4; d++) {
            const int jb = 4 * d;
            y[SW(ob + (jb    )*s)] = cmul(wr, v[d]);
            y[SW(ob + (jb + 1)*s)] = cmul(cmul(wr, w1), v[4 + d]);
            y[SW(ob + (jb + 2)*s)] = cmul(cmul(wr, w2), v[8 + d]);
            y[SW(ob + (jb + 3)*s)] = cmul(cmul(wr, w3), v[12 + d]);
            if (d < 3) wr = cmul(wr, w4);
        }
    }
}

// Final twiddle-free radix-2 round for the 8192 FFT (s = 4096).
__device__ __forceinline__ void r2_round(const float2* __restrict__ x,
                                         float2* __restrict__ y, bool half)
{
    for (int id = threadIdx.x; id < 4096; id += BS) {
        float2 a = x[SW(id)], b = x[SW(id + 4096)];
        y[SW(id)] = make_float2(a.x + b.x, a.y + b.y);
        if (!half) y[SW(id + 4096)] = make_float2(a.x - b.x, a.y - b.y);
    }
}

// 4096-pt complex FFT: 3 radix-16 rounds. Input x, result lands in y.
template<int DIR>
__device__ void cfft4096(float2* x, float2* y, const float2* TW)
{
    r16_round<DIR,false>(x, y, 12, 0, TW, 256, 256); __syncthreads();
    r16_round<DIR,false>(y, x,  8, 4, TW, 256, 256); __syncthreads();
    r16_round<DIR,false>(x, y,  4, 8, TW, 256, 256); __syncthreads();
}

// 8192-pt complex FFT: 3 radix-16 rounds + final radix-2. Result lands in x.
// ZHI: treat x[4096..8191] as zero in round 1. half_last: only store the
// lower 4096 outputs of the final round.
template<int DIR, bool ZHI>
__device__ void cfft8192(float2* x, float2* y, const float2* TW, bool half_last)
{
    r16_round<DIR,ZHI  >(x, y, 13, 0, TW, 512, 512); __syncthreads();
    r16_round<DIR,false>(y, x,  9, 4, TW, 512, 512); __syncthreads();
    r16_round<DIR,false>(x, y,  5, 8, TW, 512, 512); __syncthreads();
    r2_round(y, x, half_last);                        __syncthreads();
}

// Real-FFT unpack: Bk = V[k], Bkk = V[Nh-k] from packed transform Z.
__device__ __forceinline__ void unpack_pair(float2 Zk, float2 Zkk, float2 W,
                                            float2& Bk, float2& Bkk)
{
    float2 Ze  = make_float2(0.5f*(Zk.x + Zkk.x), 0.5f*(Zk.y - Zkk.y));
    float2 Zo  = make_float2(0.5f*(Zk.y + Zkk.y), -0.5f*(Zk.x - Zkk.x));
    float2 WZo = cmul(W, Zo);
    Bk  = make_float2(Ze.x + WZo.x, Ze.y + WZo.y);
    Bkk = make_float2(Ze.x - WZo.x, WZo.y - Ze.y);
}

__device__ __forceinline__ void repack_pair(float2 Uk, float2 Ukk, float2 W,
                                            float2& zk, float2& zkk)
{
    float2 Eu = make_float2(0.5f*(Uk.x + Ukk.x), 0.5f*(Uk.y - Ukk.y));
    float2 D  = make_float2(0.5f*(Uk.x - Ukk.x), 0.5f*(Uk.y + Ukk.y));
    float2 Wc = make_float2(W.x, -W.y);
    float2 Ou = cmul(D, Wc);
    zk  = make_float2(Eu.x - Ou.y, Eu.y + Ou.x);
    zkk = make_float2(Eu.x + Ou.y, Ou.x - Eu.y);
}

__device__ float block_reduce_sum(float v, float* red)
{
    __syncthreads();
    #pragma unroll
    for (int o = 16; o; o >>= 1) v += __shfl_down_sync(0xffffffffu, v, o);
    if ((threadIdx.x & 31) == 0) red[threadIdx.x >> 5] = v;
    __syncthreads();
    if (threadIdx.x < 32) {
        float t = (threadIdx.x < 16) ? red[threadIdx.x] : 0.0f;
        #pragma unroll
        for (int o = 8; o; o >>= 1) t += __shfl_down_sync(0xffffffffu, t, o);
        if (threadIdx.x == 0) red[0] = t;
    }
    __syncthreads();
    return red[0];
}

// Fused unpack * Fc * repack, in place on Z[0..4095] (Nh=4096, N=8192).
__device__ __forceinline__ void specA(float2* Z, const float2* __restrict__ Fc,
                                      const float2* __restrict__ TW)
{
    for (int k = threadIdx.x; k <= 2048; k += BS) {
        const int kk = (4096 - k) & 4095;
        float2 t = TW[k << 1];
        float2 W = make_float2(t.x, -t.y);
        float2 Bk, Bkk;
        unpack_pair(Z[SW(k)], Z[SW(kk)], W, Bk, Bkk);
        float2 Uk  = cmul(Bk,  Fc[k]);
        float2 Ukk = cmul(Bkk, Fc[4096 - k]);
        float2 zk, zkk;
        repack_pair(Uk, Ukk, W, zk, zkk);
        Z[SW(k)] = zk;
        if (k != 0) Z[SW(kk)] = zkk;
    }
}

// Fused unpack * Ft(real) * repack, in place on Z[0..8191] (Nh=8192, N=16384).
__device__ __forceinline__ void specB(float2* Z, const float* __restrict__ Ft,
                                      const float2* __restrict__ TW)
{
    for (int k = threadIdx.x; k <= 4096; k += BS) {
        const int kk = (8192 - k) & 8191;
        float2 t = TW[k];
        float2 W = make_float2(t.x, -t.y);
        float2 Bk, Bkk;
        unpack_pair(Z[SW(k)], Z[SW(kk)], W, Bk, Bkk);
        const float fk  = Ft[k];
        const float fkk = Ft[8192 - k];
        float2 Uk  = make_float2(Bk.x * fk,  Bk.y * fk);
        float2 Ukk = make_float2(Bkk.x * fkk, Bkk.y * fkk);
        float2 zk, zkk;
        repack_pair(Uk, Ukk, W, zk, zkk);
        Z[SW(k)] = zk;
        if (k != 0) Z[SW(kk)] = zkk;
    }
}

__global__ void __launch_bounds__(BS)
power_kernel(const float* __restrict__ gx, const float* __restrict__ gc,
             const float* __restrict__ gb0)
{
    extern __shared__ float2 smem2[];
    float2* buf0 = smem2;               // 8192
    float2* buf1 = smem2 + 8192;        // 8192
    float2* Fc   = smem2 + 16384;       // 4097
    float2* TW   = smem2 + 20481;       // 4097 : (cos,sin)(2*pi*r/16384)
    float*  Ft   = (float*)(smem2 + 24578); // 8194
    float*  red  = Ft + 8194;           // 32

    const int tid = threadIdx.x;
    const int row = blockIdx.x;
    const float* xr = gx  + (size_t)row * 8192;
    const float* cr = gc  + (size_t)row * 8192;
    const float* br = gb0 + (size_t)row * 8192;

    // ---- twiddle table ----
    for (int r = tid; r <= 4096; r += BS) {
        float sv, cv;
        sincospif((float)r * (1.0f / 8192.0f), &sv, &cv);
        TW[r] = make_float2(cv, sv);
    }
    __syncthreads();

    // ---- Fc = DFT_8192(circ) / 4096 (half spectrum) ----
    for (int n = tid; n < 4096; n += BS)
        buf0[SW(n)] = make_float2(cr[2*n], cr[2*n + 1]);
    __syncthreads();
    cfft4096<-1>(buf0, buf1, TW);                 // result in buf1
    {
        float2* Z = buf1;
        const float sc = 1.0f / 4096.0f;
        for (int k = tid; k <= 2048; k += BS) {
            const int kk = (4096 - k) & 4095;
            float2 t = TW[k << 1];
            float2 W = make_float2(t.x, -t.y);
            float2 Bk, Bkk;
            unpack_pair(Z[SW(k)], Z[SW(kk)], W, Bk, Bkk);
            Fc[k]        = make_float2(Bk.x * sc,  Bk.y * sc);
            Fc[4096 - k] = make_float2(Bkk.x * sc, Bkk.y * sc);
        }
    }
    __syncthreads();

    // ---- Ft = Re(DFT_16384([x, 0, flip(x[1:])])) / 8192 (real half spectrum) ----
    for (int n = tid; n < 8192; n += BS) {
        const int j0 = 2*n, j1 = 2*n + 1;
        float e0 = (j0 < 8192) ? xr[j0] : ((j0 == 8192) ? 0.0f : xr[16384 - j0]);
        float e1 = (j1 < 8192) ? xr[j1] : xr[16384 - j1];
        buf0[SW(n)] = make_float2(e0, e1);
    }
    __syncthreads();
    cfft8192<-1,false>(buf0, buf1, TW, false);    // result in buf0
    {
        float2* Z = buf0;
        const float sc = 1.0f / 8192.0f;
        for (int k = tid; k <= 4096; k += BS) {
            const int kk = (8192 - k) & 8191;
            float2 t = TW[k];
            float2 W = make_float2(t.x, -t.y);
            float2 Bk, Bkk;
            unpack_pair(Z[SW(k)], Z[SW(kk)], W, Bk, Bkk);
            Ft[k]        = Bk.x * sc;
            Ft[8192 - k] = Bkk.x * sc;
        }
    }
    __syncthreads();

    // ---- b = b0 / ||b0||, thread t owns b[16t .. 16t+15] ----
    float b[16];
    {
        #pragma unroll
        for (int q4 = 0; q4 < 4; q4++) {
            const float4 v = *(const float4*)(br + tid*16 + q4*4);
            b[q4*4+0] = v.x; b[q4*4+1] = v.y; b[q4*4+2] = v.z; b[q4*4+3] = v.w;
        }
        float ss = 0.0f;
        #pragma unroll
        for (int i = 0; i < 16; i++) ss += b[i]*b[i];
        float tot = block_reduce_sum(ss, red);
        float inv = 1.0f / sqrtf(tot);
        #pragma unroll
        for (int i = 0; i < 16; i++) b[i] *= inv;
    }

    // ---- 100 power iterations + 1 final application ----
    for (int it = 0; it <= 100; ++it) {
        // pack b: buf0[n] = (b[2n], b[2n+1]), n = 8*tid + j
        #pragma unroll
        for (int j = 0; j < 8; ++j)
            buf0[SW(8*tid + j)] = make_float2(b[2*j], b[2*j + 1]);
        __syncthreads();

        // u = IFFT( Fc * FFT(b) )   (8192-pt real conv via 4096-pt CFFT)
        cfft4096<-1>(buf0, buf1, TW);             // -> buf1
        specA(buf1, Fc, TW);
        __syncthreads();
        cfft4096<+1>(buf1, buf0, TW);             // -> buf0 : packed u

        // w = first 8192 of IFFT_16384( Ft * FFT_16384([u,0]) )
        cfft8192<-1,true >(buf0, buf1, TW, false); // zero-pad fused; -> buf0
        specB(buf0, Ft, TW);
        __syncthreads();
        cfft8192<+1,false>(buf0, buf1, TW, true);  // lower half only; -> buf0

        float w_[16];
        #pragma unroll
        for (int j = 0; j < 8; ++j) {
            float2 v = buf0[SW(8*tid + j)];
            w_[2*j]     = v.x;
            w_[2*j + 1] = v.y;
        }

        if (it < 100) {
            float nb[16];
            float ss = 0.0f;
            #pragma unroll
            for (int i = 0; i < 16; i++) { nb[i] = b[i] - w_[i]; ss += nb[i]*nb[i]; }
            float tot = block_reduce_sum(ss, red);
            float inv = 1.0f / sqrtf(tot);
            #pragma unroll
            for (int i = 0; i < 16; i++) b[i] = nb[i] * inv;
        } else {
            float dp = 0.0f;
            #pragma unroll
            for (int i = 0; i < 16; i++) dp += b[i] * w_[i];
            float tot = block_reduce_sum(dp, red);
            if (tid == 0) g_sigma[row] = 1.0f - tot;   // sigma = b.(b-w) = 1 - b.w
        }
    }
}

__global__ void finalize_kernel(float* __restrict__ out)
{
    __shared__ float red[16];
    const int t = threadIdx.x;   // 512 threads
    float v = fabsf(g_sigma[t]);
    #pragma unroll
    for (int o = 16; o; o >>= 1) v += __shfl_down_sync(0xffffffffu, v, o);
    if ((t & 31) == 0) red[t >> 5] = v;
    __syncthreads();
    if (t < 16) {
        float s = red[t];
        #pragma unroll
        for (int o = 8; o; o >>= 1) s += __shfl_down_sync(0xffffu, s, o);
        if (t == 0) out[0] = s * (1.0f / 512.0f);
    }
}

extern "C" void kernel_launch(void* const* d_in, const int* in_sizes, int n_in,
                              void* d_out, int out_size)
{
    (void)in_sizes; (void)n_in; (void)out_size;
    const float* x    = (const float*)d_in[0];
    const float* circ = (const float*)d_in[1];
    const float* b0   = (const float*)d_in[2];

    cudaFuncSetAttribute(power_kernel,
                         cudaFuncAttributeMaxDynamicSharedMemorySize, SMEM_BYTES);
    power_kernel<<<NROW, BS, SMEM_BYTES>>>(x, circ, b0);
    finalize_kernel<<<1, 512>>>((float*)d_out);
}

// round 6
// speedup vs baseline: 1.0356x; 1.0354x over previous
#include <cuda_runtime.h>
#include <math.h>

#define BS   512
#define NROW 512
// smem: buf0(8192 c) + buf1(8192 c) + Fc(4097 c) + TW(4097 c) + Ft(8194 f) + red(32 f)
#define SMEM_BYTES (24578*8 + 8226*4)

typedef unsigned long long u64c;

__device__ float g_sigma[NROW];

__device__ __forceinline__ int SW(int i) { return i ^ ((i >> 5) & 31); }

// ---------------- packed f32x2 primitives (sm_103a) ----------------
__device__ __forceinline__ u64c pk(float x, float y) {
    u64c r; asm("mov.b64 %0,{%1,%2};" : "=l"(r) : "f"(x), "f"(y)); return r;
}
__device__ __forceinline__ void unpk(u64c a, float& x, float& y) {
    asm("mov.b64 {%0,%1},%2;" : "=f"(x), "=f"(y) : "l"(a));
}
__device__ __forceinline__ u64c add2(u64c a, u64c b) {
    u64c r; asm("add.rn.f32x2 %0,%1,%2;" : "=l"(r) : "l"(a), "l"(b)); return r;
}
__device__ __forceinline__ u64c mul2(u64c a, u64c b) {
    u64c r; asm("mul.rn.f32x2 %0,%1,%2;" : "=l"(r) : "l"(a), "l"(b)); return r;
}
__device__ __forceinline__ u64c fma2(u64c a, u64c b, u64c c) {
    u64c r; asm("fma.rn.f32x2 %0,%1,%2,%3;" : "=l"(r) : "l"(a), "l"(b), "l"(c)); return r;
}
__device__ __forceinline__ u64c sub2(u64c a, u64c b) { return fma2(b, pk(-1.f, -1.f), a); }
__device__ __forceinline__ u64c swp(u64c a) { float x, y; unpk(a, x, y); return pk(y, x); }

__device__ __forceinline__ float2 cmul(float2 a, float2 b) {
    return make_float2(a.x*b.x - a.y*b.y, a.x*b.y + a.y*b.x);
}
// scalar complex w times packed complex v
__device__ __forceinline__ u64c cmulps(float2 w, u64c v) {
    float vx, vy; unpk(v, vx, vy);
    return pk(fmaf(w.x, vx, -w.y * vy), fmaf(w.x, vy, w.y * vx));
}
// packed v times constant twiddle (c, ds): (c*vx - ds*vy, c*vy + ds*vx)
__device__ __forceinline__ u64c ct(u64c v, float c, float ds) {
    return fma2(swp(v), pk(-ds, ds), mul2(pk(c, c), v));
}

// ---------------- packed radix-4 ----------------
template<int DIR>
__device__ __forceinline__ void dft4p(u64c& a, u64c& b, u64c& c, u64c& d) {
    u64c apc = add2(a, c), amc = sub2(a, c);
    u64c bpd = add2(b, d), bmd = sub2(b, d);
    a = add2(apc, bpd);
    c = sub2(apc, bpd);
    u64c s = swp(bmd);
    const float D = (DIR > 0) ? 1.f : -1.f;
    b = fma2(s, pk(-D, D), amc);   // amc + i*D*bmd
    d = fma2(s, pk(D, -D), amc);   // amc - i*D*bmd
}
// radix-4 with c=d=0 (fused zero-pad): out of (a,b,0,0)
template<int DIR>
__device__ __forceinline__ void dft4pz(u64c a, u64c b,
                                       u64c& o0, u64c& o1, u64c& o2, u64c& o3) {
    const float D = (DIR > 0) ? 1.f : -1.f;
    u64c s = swp(b);
    o0 = add2(a, b);
    o2 = sub2(a, b);
    o1 = fma2(s, pk(-D, D), a);
    o3 = fma2(s, pk(D, -D), a);
}

template<int DIR>
__device__ __forceinline__ void applyW16p(u64c* v) {
    const float C1 = 0.9238795325112867f, S1 = 0.3826834323650898f;
    const float H  = 0.7071067811865476f;
    const float D  = (DIR > 0) ? 1.f : -1.f;
    v[5]  = ct(v[5],  C1,  D*S1);
    v[9]  = ct(v[9],   H,  D*H);
    v[13] = ct(v[13], S1,  D*C1);
    v[6]  = ct(v[6],   H,  D*H);
    v[10] = mul2(swp(v[10]), pk(-D, D));   // * (0, D)
    v[14] = ct(v[14], -H,  D*H);
    v[7]  = ct(v[7],  S1,  D*C1);
    v[11] = ct(v[11], -H,  D*H);
    v[15] = ct(v[15], -C1, -D*S1);
}

// ---------------- one radix-16 Stockham round (compile-time shape) ----------------
template<int DIR, int LGS, int R, bool ZHI>
__device__ __forceinline__ void r16_round(const float2* __restrict__ xf,
                                          float2* __restrict__ yf,
                                          const float2* __restrict__ TW)
{
    constexpr int NBF   = 1 << (LGS - 4);
    constexpr int LS    = 4 * R;
    constexpr int S     = 1 << LS;
    constexpr int SHIFT = 14 - (LGS - LS);
    const u64c* x = (const u64c*)xf;
    u64c*       y = (u64c*)yf;
    const int id = threadIdx.x;
    if (NBF < BS && id >= NBF) return;
    const int q  = id & (S - 1);
    const int p  = id >> LS;
    const int ib = q + (p << LS);

    u64c v[16];
    if (ZHI) {
        #pragma unroll
        for (int r = 0; r < 8; r++) v[r] = x[SW(ib + r * NBF)];
        #pragma unroll
        for (int bb = 0; bb < 4; bb++)
            dft4pz<DIR>(v[bb], v[bb+4], v[bb], v[bb+4], v[bb+8], v[bb+12]);
    } else {
        #pragma unroll
        for (int r = 0; r < 16; r++) v[r] = x[SW(ib + r * NBF)];
        #pragma unroll
        for (int bb = 0; bb < 4; bb++)
            dft4p<DIR>(v[bb], v[bb+4], v[bb+8], v[bb+12]);
    }
    applyW16p<DIR>(v);
    #pragma unroll
    for (int c = 0; c < 4; c++)
        dft4p<DIR>(v[4*c], v[4*c+1], v[4*c+2], v[4*c+3]);

    const int ob = q + ((p << 4) << LS);
    if (R == 2 && p == 0) {
        // all stage twiddles are 1 (out j = c+4d from slot v[4c+d])
        y[SW(ob       )] = v[0];  y[SW(ob +    S)] = v[4];
        y[SW(ob +  2*S)] = v[8];  y[SW(ob +  3*S)] = v[12];
        y[SW(ob +  4*S)] = v[1];  y[SW(ob +  5*S)] = v[5];
        y[SW(ob +  6*S)] = v[9];  y[SW(ob +  7*S)] = v[13];
        y[SW(ob +  8*S)] = v[2];  y[SW(ob +  9*S)] = v[6];
        y[SW(ob + 10*S)] = v[10]; y[SW(ob + 11*S)] = v[14];
        y[SW(ob + 12*S)] = v[3];  y[SW(ob + 13*S)] = v[7];
        y[SW(ob + 14*S)] = v[11]; y[SW(ob + 15*S)] = v[15];
    } else {
        float2 t  = TW[p << SHIFT];
        float2 w1 = make_float2(t.x, (DIR > 0) ? t.y : -t.y);
        float2 w2 = cmul(w1, w1);
        float2 w3 = cmul(w2, w1);
        float2 w4 = cmul(w2, w2);
        y[SW(ob       )] = v[0];
        y[SW(ob +    S)] = cmulps(w1, v[4]);
        y[SW(ob +  2*S)] = cmulps(w2, v[8]);
        y[SW(ob +  3*S)] = cmulps(w3, v[12]);
        float2 wr = w4;
        #pragma unroll
        for (int d = 1; d < 4; d++) {
            const int jb = 4 * d;
            y[SW(ob + (jb    )*S)] = cmulps(wr, v[d]);
            y[SW(ob + (jb + 1)*S)] = cmulps(cmul(wr, w1), v[4 + d]);
            y[SW(ob + (jb + 2)*S)] = cmulps(cmul(wr, w2), v[8 + d]);
            y[SW(ob + (jb + 3)*S)] = cmulps(cmul(wr, w3), v[12 + d]);
            if (d < 3) wr = cmul(wr, w4);
        }
    }
}

// plain final radix-2 for the 8192 FFT (preamble only): B = r2(A)
__device__ void r2_full(const float2* __restrict__ A, float2* __restrict__ B)
{
    for (int id = threadIdx.x; id < 4096; id += BS) {
        float2 a = A[SW(id)], b = A[SW(id + 4096)];
        B[SW(id)]        = make_float2(a.x + b.x, a.y + b.y);
        B[SW(id + 4096)] = make_float2(a.x - b.x, a.y - b.y);
    }
}

// ---------------- real-FFT pack/unpack ----------------
__device__ __forceinline__ void unpack_pair(float2 Zk, float2 Zkk, float2 W,
                                            float2& Bk, float2& Bkk)
{
    float2 Ze  = make_float2(0.5f*(Zk.x + Zkk.x), 0.5f*(Zk.y - Zkk.y));
    float2 Zo  = make_float2(0.5f*(Zk.y + Zkk.y), -0.5f*(Zk.x - Zkk.x));
    float2 WZo = cmul(W, Zo);
    Bk  = make_float2(Ze.x + WZo.x, Ze.y + WZo.y);
    Bkk = make_float2(Ze.x - WZo.x, WZo.y - Ze.y);
}
__device__ __forceinline__ void repack_pair(float2 Uk, float2 Ukk, float2 W,
                                            float2& zk, float2& zkk)
{
    float2 Eu = make_float2(0.5f*(Uk.x + Ukk.x), 0.5f*(Uk.y - Ukk.y));
    float2 D  = make_float2(0.5f*(Uk.x - Ukk.x), 0.5f*(Uk.y + Ukk.y));
    float2 Wc = make_float2(W.x, -W.y);
    float2 Ou = cmul(D, Wc);
    zk  = make_float2(Eu.x - Ou.y, Eu.y + Ou.x);
    zkk = make_float2(Eu.x + Ou.y, Ou.x - Eu.y);
}

// one spectral pair of the Toeplitz multiply (real transfer Ft)
__device__ __forceinline__ void pairB(int k, float2 Zk, float2 Zkk,
                                      const float* __restrict__ Ft,
                                      const float2* __restrict__ TW,
                                      float2& zk, float2& zkk)
{
    float2 t = TW[k];
    float2 W = make_float2(t.x, -t.y);
    float2 Bk, Bkk;
    unpack_pair(Zk, Zkk, W, Bk, Bkk);
    const float fk  = Ft[k];
    const float fkk = Ft[8192 - k];
    float2 Uk  = make_float2(Bk.x * fk,  Bk.y * fk);
    float2 Ukk = make_float2(Bkk.x * fkk, Bkk.y * fkk);
    repack_pair(Uk, Ukk, W, zk, zkk);
}

// fused: final radix-2 of fwd CFFT_8192 + specB. Reads A (post 3 r16 rounds),
// writes repacked spectrum to B. Item j owns butterflies j and 4096-j, which
// produce exactly spectral pairs (j, 8192-j) and (4096-j, 4096+j).
__device__ void r2_specB(const float2* __restrict__ A, float2* __restrict__ B,
                         const float* __restrict__ Ft, const float2* __restrict__ TW)
{
    for (int j = threadIdx.x; j <= 2048; j += BS) {
        float2 a0 = A[SW(j)], b0 = A[SW(j + 4096)];
        float2 Zj0 = make_float2(a0.x + b0.x, a0.y + b0.y);   // Z[j]
        float2 Zj1 = make_float2(a0.x - b0.x, a0.y - b0.y);   // Z[j+4096]
        if (j == 0) {
            float2 zk, zkk;
            pairB(0, Zj0, Zj0, Ft, TW, zk, zkk);
            B[SW(0)] = zk;
            pairB(4096, Zj1, Zj1, Ft, TW, zk, zkk);
            B[SW(4096)] = zk;
        } else if (j == 2048) {
            float2 zk, zkk;
            pairB(2048, Zj0, Zj1, Ft, TW, zk, zkk);
            B[SW(2048)] = zk;
            B[SW(6144)] = zkk;
        } else {
            float2 a1 = A[SW(4096 - j)], b1 = A[SW(8192 - j)];
            float2 Zm0 = make_float2(a1.x + b1.x, a1.y + b1.y); // Z[4096-j]
            float2 Zm1 = make_float2(a1.x - b1.x, a1.y - b1.y); // Z[8192-j]
            float2 zk, zkk;
            pairB(j, Zj0, Zm1, Ft, TW, zk, zkk);
            B[SW(j)]        = zk;
            B[SW(8192 - j)] = zkk;
            pairB(4096 - j, Zm0, Zj1, Ft, TW, zk, zkk);
            B[SW(4096 - j)] = zk;
            B[SW(4096 + j)] = zkk;
        }
    }
}

__device__ float block_reduce_sum(float v, float* red)
{
    __syncthreads();
    #pragma unroll
    for (int o = 16; o; o >>= 1) v += __shfl_down_sync(0xffffffffu, v, o);
    if ((threadIdx.x & 31) == 0) red[threadIdx.x >> 5] = v;
    __syncthreads();
    if (threadIdx.x < 32) {
        float t = (threadIdx.x < 16) ? red[threadIdx.x] : 0.0f;
        #pragma unroll
        for (int o = 8; o; o >>= 1) t += __shfl_down_sync(0xffffffffu, t, o);
        if (threadIdx.x == 0) red[0] = t;
    }
    __syncthreads();
    return red[0];
}

// Fused unpack * Fc * repack, in place on Z[0..4095] (Nh=4096, N=8192).
__device__ void specA(float2* Z, const float2* __restrict__ Fc,
                      const float2* __restrict__ TW)
{
    for (int k = threadIdx.x; k <= 2048; k += BS) {
        const int kk = (4096 - k) & 4095;
        float2 t = TW[k << 1];
        float2 W = make_float2(t.x, -t.y);
        float2 Bk, Bkk;
        unpack_pair(Z[SW(k)], Z[SW(kk)], W, Bk, Bkk);
        float2 Uk  = cmul(Bk,  Fc[k]);
        float2 Ukk = cmul(Bkk, Fc[4096 - k]);
        float2 zk, zkk;
        repack_pair(Uk, Ukk, W, zk, zkk);
        Z[SW(k)] = zk;
        if (k != 0) Z[SW(kk)] = zkk;
    }
}

__global__ void __launch_bounds__(BS)
power_kernel(const float* __restrict__ gx, const float* __restrict__ gc,
             const float* __restrict__ gb0)
{
    extern __shared__ float2 smem2[];
    float2* buf0 = smem2;               // 8192
    float2* buf1 = smem2 + 8192;        // 8192
    float2* Fc   = smem2 + 16384;       // 4097
    float2* TW   = smem2 + 20481;       // 4097 : (cos,sin)(2*pi*r/16384)
    float*  Ft   = (float*)(smem2 + 24578); // 8194
    float*  red  = Ft + 8194;           // 32

    const int tid = threadIdx.x;
    const int row = blockIdx.x;
    const float* xr = gx  + (size_t)row * 8192;
    const float* cr = gc  + (size_t)row * 8192;
    const float* br = gb0 + (size_t)row * 8192;

    // ---- twiddle table ----
    for (int r = tid; r <= 4096; r += BS) {
        float sv, cv;
        sincospif((float)r * (1.0f / 8192.0f), &sv, &cv);
        TW[r] = make_float2(cv, sv);
    }
    __syncthreads();

    // ---- Fc = DFT_8192(circ) / 4096 (half spectrum) ----
    for (int n = tid; n < 4096; n += BS)
        buf0[SW(n)] = make_float2(cr[2*n], cr[2*n + 1]);
    __syncthreads();
    r16_round<-1,12,0,false>(buf0, buf1, TW); __syncthreads();
    r16_round<-1,12,1,false>(buf1, buf0, TW); __syncthreads();
    r16_round<-1,12,2,false>(buf0, buf1, TW); __syncthreads();
    {
        float2* Z = buf1;
        const float sc = 1.0f / 4096.0f;
        for (int k = tid; k <= 2048; k += BS) {
            const int kk = (4096 - k) & 4095;
            float2 t = TW[k << 1];
            float2 W = make_float2(t.x, -t.y);
            float2 Bk, Bkk;
            unpack_pair(Z[SW(k)], Z[SW(kk)], W, Bk, Bkk);
            Fc[k]        = make_float2(Bk.x * sc,  Bk.y * sc);
            Fc[4096 - k] = make_float2(Bkk.x * sc, Bkk.y * sc);
        }
    }
    __syncthreads();

    // ---- Ft = Re(DFT_16384([x, 0, flip(x[1:])])) / 8192 (real half spectrum) ----
    for (int n = tid; n < 8192; n += BS) {
        const int j0 = 2*n, j1 = 2*n + 1;
        float e0 = (j0 < 8192) ? xr[j0] : ((j0 == 8192) ? 0.0f : xr[16384 - j0]);
        float e1 = (j1 < 8192) ? xr[j1] : xr[16384 - j1];
        buf0[SW(n)] = make_float2(e0, e1);
    }
    __syncthreads();
    r16_round<-1,13,0,false>(buf0, buf1, TW); __syncthreads();
    r16_round<-1,13,1,false>(buf1, buf0, TW); __syncthreads();
    r16_round<-1,13,2,false>(buf0, buf1, TW); __syncthreads();
    r2_full(buf1, buf0);                      __syncthreads();
    {
        float2* Z = buf0;
        const float sc = 1.0f / 8192.0f;
        for (int k = tid; k <= 4096; k += BS) {
            const int kk = (8192 - k) & 8191;
            float2 t = TW[k];
            float2 W = make_float2(t.x, -t.y);
            float2 Bk, Bkk;
            unpack_pair(Z[SW(k)], Z[SW(kk)], W, Bk, Bkk);
            Ft[k]        = Bk.x * sc;
            Ft[8192 - k] = Bkk.x * sc;
        }
    }
    __syncthreads();

    // ---- b = b0 / ||b0||, thread t owns b[16t .. 16t+15] ----
    float b[16];
    {
        #pragma unroll
        for (int q4 = 0; q4 < 4; q4++) {
            const float4 v = *(const float4*)(br + tid*16 + q4*4);
            b[q4*4+0] = v.x; b[q4*4+1] = v.y; b[q4*4+2] = v.z; b[q4*4+3] = v.w;
        }
        float ss = 0.0f;
        #pragma unroll
        for (int i = 0; i < 16; i++) ss += b[i]*b[i];
        float tot = block_reduce_sum(ss, red);
        float inv = 1.0f / sqrtf(tot);
        #pragma unroll
        for (int i = 0; i < 16; i++) b[i] *= inv;
    }

    // ---- 100 power iterations + 1 final application ----
    for (int it = 0; it <= 100; ++it) {
        // pack b: buf0[n] = (b[2n], b[2n+1]), n = 8*tid + j
        #pragma unroll
        for (int j = 0; j < 8; ++j)
            buf0[SW(8*tid + j)] = make_float2(b[2*j], b[2*j + 1]);
        __syncthreads();

        // u = IFFT( Fc * FFT(b) )   (8192-pt real conv via 4096-pt CFFT)
        r16_round<-1,12,0,false>(buf0, buf1, TW); __syncthreads();
        r16_round<-1,12,1,false>(buf1, buf0, TW); __syncthreads();
        r16_round<-1,12,2,false>(buf0, buf1, TW); __syncthreads();
        specA(buf1, Fc, TW);                      __syncthreads();
        r16_round<+1,12,0,false>(buf1, buf0, TW); __syncthreads();
        r16_round<+1,12,1,false>(buf0, buf1, TW); __syncthreads();
        r16_round<+1,12,2,false>(buf1, buf0, TW); __syncthreads();
        // buf0 now holds packed u; upper 4096 treated as zero via ZHI.

        // w = first 8192 of IFFT_16384( Ft * FFT_16384([u,0]) )
        r16_round<-1,13,0,true >(buf0, buf1, TW); __syncthreads();
        r16_round<-1,13,1,false>(buf1, buf0, TW); __syncthreads();
        r16_round<-1,13,2,false>(buf0, buf1, TW); __syncthreads();
        r2_specB(buf1, buf0, Ft, TW);             __syncthreads();
        r16_round<+1,13,0,false>(buf0, buf1, TW); __syncthreads();
        r16_round<+1,13,1,false>(buf1, buf0, TW); __syncthreads();
        r16_round<+1,13,2,false>(buf0, buf1, TW); __syncthreads();

        // final radix-2 straight into registers: w[n], n = 16t..16t+15
        float w_[16];
        #pragma unroll
        for (int j = 0; j < 8; ++j) {
            const int id = 8*tid + j;
            float2 a = buf1[SW(id)], bb2 = buf1[SW(id + 4096)];
            w_[2*j]     = a.x + bb2.x;
            w_[2*j + 1] = a.y + bb2.y;
        }

        if (it < 100) {
            float nb[16];
            float ss = 0.0f;
            #pragma unroll
            for (int i = 0; i < 16; i++) { nb[i] = b[i] - w_[i]; ss += nb[i]*nb[i]; }
            float tot = block_reduce_sum(ss, red);
            float inv = 1.0f / sqrtf(tot);
            #pragma unroll
            for (int i = 0; i < 16; i++) b[i] = nb[i] * inv;
        } else {
            float dp = 0.0f;
            #pragma unroll
            for (int i = 0; i < 16; i++) dp += b[i] * w_[i];
            float tot = block_reduce_sum(dp, red);
            if (tid == 0) g_sigma[row] = 1.0f - tot;   // sigma = b.(b-w) = 1 - b.w
        }
    }
}

__global__ void finalize_kernel(float* __restrict__ out)
{
    __shared__ float red[16];
    const int t = threadIdx.x;   // 512 threads
    float v = fabsf(g_sigma[t]);
    #pragma unroll
    for (int o = 16; o; o >>= 1) v += __shfl_down_sync(0xffffffffu, v, o);
    if ((t & 31) == 0) red[t >> 5] = v;
    __syncthreads();
    if (t < 16) {
        float s = red[t];
        #pragma unroll
        for (int o = 8; o; o >>= 1) s += __shfl_down_sync(0xffffu, s, o);
        if (t == 0) out[0] = s * (1.0f / 512.0f);
    }
}

extern "C" void kernel_launch(void* const* d_in, const int* in_sizes, int n_in,
                              void* d_out, int out_size)
{
    (void)in_sizes; (void)n_in; (void)out_size;
    const float* x    = (const float*)d_in[0];
    const float* circ = (const float*)d_in[1];
    const float* b0   = (const float*)d_in[2];

    cudaFuncSetAttribute(power_kernel,
                         cudaFuncAttributeMaxDynamicSharedMemorySize, SMEM_BYTES);
    power_kernel<<<NROW, BS, SMEM_BYTES>>>(x, circ, b0);
    finalize_kernel<<<1, 512>>>((float*)d_out);
}

// round 7
// speedup vs baseline: 1.0362x; 1.0006x over previous
#include <cuda_runtime.h>
#include <math.h>

#define BS   512
#define NROW 512
// smem: buf0(8192 c) + buf1(8192 c) + Fc(4097 c) + TW(4097 c) + Ft(8194 f) + red(32 f)
#define SMEM_BYTES (24578*8 + 8226*4)

typedef unsigned long long u64c;

__device__ float g_sigma[NROW];

__device__ __forceinline__ int SW(int i) { return i ^ ((i >> 5) & 31); }

// ---------------- packed f32x2 primitives (sm_103a) ----------------
__device__ __forceinline__ u64c pk(float x, float y) {
    u64c r; asm("mov.b64 %0,{%1,%2};" : "=l"(r) : "f"(x), "f"(y)); return r;
}
__device__ __forceinline__ void unpk(u64c a, float& x, float& y) {
    asm("mov.b64 {%0,%1},%2;" : "=f"(x), "=f"(y) : "l"(a));
}
__device__ __forceinline__ u64c add2(u64c a, u64c b) {
    u64c r; asm("add.rn.f32x2 %0,%1,%2;" : "=l"(r) : "l"(a), "l"(b)); return r;
}
__device__ __forceinline__ u64c mul2(u64c a, u64c b) {
    u64c r; asm("mul.rn.f32x2 %0,%1,%2;" : "=l"(r) : "l"(a), "l"(b)); return r;
}
__device__ __forceinline__ u64c fma2(u64c a, u64c b, u64c c) {
    u64c r; asm("fma.rn.f32x2 %0,%1,%2,%3;" : "=l"(r) : "l"(a), "l"(b), "l"(c)); return r;
}
__device__ __forceinline__ u64c sub2(u64c a, u64c b) { return fma2(b, pk(-1.f, -1.f), a); }
__device__ __forceinline__ u64c swp(u64c a) { float x, y; unpk(a, x, y); return pk(y, x); }

__device__ __forceinline__ float2 cmul(float2 a, float2 b) {
    return make_float2(a.x*b.x - a.y*b.y, a.x*b.y + a.y*b.x);
}
// scalar complex w times packed complex v
__device__ __forceinline__ u64c cmulps(float2 w, u64c v) {
    float vx, vy; unpk(v, vx, vy);
    return pk(fmaf(w.x, vx, -w.y * vy), fmaf(w.x, vy, w.y * vx));
}
// packed v times constant twiddle (c, ds): (c*vx - ds*vy, c*vy + ds*vx)
__device__ __forceinline__ u64c ct(u64c v, float c, float ds) {
    return fma2(swp(v), pk(-ds, ds), mul2(pk(c, c), v));
}

// ---------------- packed radix-4 ----------------
template<int DIR>
__device__ __forceinline__ void dft4p(u64c& a, u64c& b, u64c& c, u64c& d) {
    u64c apc = add2(a, c), amc = sub2(a, c);
    u64c bpd = add2(b, d), bmd = sub2(b, d);
    a = add2(apc, bpd);
    c = sub2(apc, bpd);
    u64c s = swp(bmd);
    const float D = (DIR > 0) ? 1.f : -1.f;
    b = fma2(s, pk(-D, D), amc);   // amc + i*D*bmd
    d = fma2(s, pk(D, -D), amc);   // amc - i*D*bmd
}
// radix-4 with c=d=0 (fused zero-pad): out of (a,b,0,0)
template<int DIR>
__device__ __forceinline__ void dft4pz(u64c a, u64c b,
                                       u64c& o0, u64c& o1, u64c& o2, u64c& o3) {
    const float D = (DIR > 0) ? 1.f : -1.f;
    u64c s = swp(b);
    o0 = add2(a, b);
    o2 = sub2(a, b);
    o1 = fma2(s, pk(-D, D), a);
    o3 = fma2(s, pk(D, -D), a);
}

template<int DIR>
__device__ __forceinline__ void applyW16p(u64c* v) {
    const float C1 = 0.9238795325112867f, S1 = 0.3826834323650898f;
    const float H  = 0.7071067811865476f;
    const float D  = (DIR > 0) ? 1.f : -1.f;
    v[5]  = ct(v[5],  C1,  D*S1);
    v[9]  = ct(v[9],   H,  D*H);
    v[13] = ct(v[13], S1,  D*C1);
    v[6]  = ct(v[6],   H,  D*H);
    v[10] = mul2(swp(v[10]), pk(-D, D));   // * (0, D)
    v[14] = ct(v[14], -H,  D*H);
    v[7]  = ct(v[7],  S1,  D*C1);
    v[11] = ct(v[11], -H,  D*H);
    v[15] = ct(v[15], -C1, -D*S1);
}

// ---------------- one radix-16 Stockham round (compile-time shape) ----------------
template<int DIR, int LGS, int R, bool ZHI>
__device__ __forceinline__ void r16_round(const float2* __restrict__ xf,
                                          float2* __restrict__ yf,
                                          const float2* __restrict__ TW)
{
    constexpr int NBF   = 1 << (LGS - 4);
    constexpr int LS    = 4 * R;
    constexpr int S     = 1 << LS;
    constexpr int SHIFT = 14 - (LGS - LS);
    const u64c* x = (const u64c*)xf;
    u64c*       y = (u64c*)yf;
    const int id = threadIdx.x;
    if (NBF < BS && id >= NBF) return;
    const int q  = id & (S - 1);
    const int p  = id >> LS;
    const int ib = q + (p << LS);

    u64c v[16];
    if (ZHI) {
        #pragma unroll
        for (int r = 0; r < 8; r++) v[r] = x[SW(ib + r * NBF)];
        #pragma unroll
        for (int bb = 0; bb < 4; bb++)
            dft4pz<DIR>(v[bb], v[bb+4], v[bb], v[bb+4], v[bb+8], v[bb+12]);
    } else {
        #pragma unroll
        for (int r = 0; r < 16; r++) v[r] = x[SW(ib + r * NBF)];
        #pragma unroll
        for (int bb = 0; bb < 4; bb++)
            dft4p<DIR>(v[bb], v[bb+4], v[bb+8], v[bb+12]);
    }
    applyW16p<DIR>(v);
    #pragma unroll
    for (int c = 0; c < 4; c++)
        dft4p<DIR>(v[4*c], v[4*c+1], v[4*c+2], v[4*c+3]);

    const int ob = q + ((p << 4) << LS);
    if (R == 2 && p == 0) {
        // all stage twiddles are 1 (out j = c+4d from slot v[4c+d])
        y[SW(ob       )] = v[0];  y[SW(ob +    S)] = v[4];
        y[SW(ob +  2*S)] = v[8];  y[SW(ob +  3*S)] = v[12];
        y[SW(ob +  4*S)] = v[1];  y[SW(ob +  5*S)] = v[5];
        y[SW(ob +  6*S)] = v[9];  y[SW(ob +  7*S)] = v[13];
        y[SW(ob +  8*S)] = v[2];  y[SW(ob +  9*S)] = v[6];
        y[SW(ob + 10*S)] = v[10]; y[SW(ob + 11*S)] = v[14];
        y[SW(ob + 12*S)] = v[3];  y[SW(ob + 13*S)] = v[7];
        y[SW(ob + 14*S)] = v[11]; y[SW(ob + 15*S)] = v[15];
    } else {
        float2 t  = TW[p << SHIFT];
        float2 w1 = make_float2(t.x, (DIR > 0) ? t.y : -t.y);
        float2 w2 = cmul(w1, w1);
        float2 w3 = cmul(w2, w1);
        float2 w4 = cmul(w2, w2);
        y[SW(ob       )] = v[0];
        y[SW(ob +    S)] = cmulps(w1, v[4]);
        y[SW(ob +  2*S)] = cmulps(w2, v[8]);
        y[SW(ob +  3*S)] = cmulps(w3, v[12]);
        float2 wr = w4;
        #pragma unroll
        for (int d = 1; d < 4; d++) {
            const int jb = 4 * d;
            y[SW(ob + (jb    )*S)] = cmulps(wr, v[d]);
            y[SW(ob + (jb + 1)*S)] = cmulps(cmul(wr, w1), v[4 + d]);
            y[SW(ob + (jb + 2)*S)] = cmulps(cmul(wr, w2), v[8 + d]);
            y[SW(ob + (jb + 3)*S)] = cmulps(cmul(wr, w3), v[12 + d]);
            if (d < 3) wr = cmul(wr, w4);
        }
    }
}

// plain final radix-2 for the 8192 FFT (preamble only): B = r2(A)
__device__ void r2_full(const float2* __restrict__ A, float2* __restrict__ B)
{
    for (int id = threadIdx.x; id < 4096; id += BS) {
        float2 a = A[SW(id)], b = A[SW(id + 4096)];
        B[SW(id)]        = make_float2(a.x + b.x, a.y + b.y);
        B[SW(id + 4096)] = make_float2(a.x - b.x, a.y - b.y);
    }
}

// ---------------- real-FFT pack/unpack ----------------
__device__ __forceinline__ void unpack_pair(float2 Zk, float2 Zkk, float2 W,
                                            float2& Bk, float2& Bkk)
{
    float2 Ze  = make_float2(0.5f*(Zk.x + Zkk.x), 0.5f*(Zk.y - Zkk.y));
    float2 Zo  = make_float2(0.5f*(Zk.y + Zkk.y), -0.5f*(Zk.x - Zkk.x));
    float2 WZo = cmul(W, Zo);
    Bk  = make_float2(Ze.x + WZo.x, Ze.y + WZo.y);
    Bkk = make_float2(Ze.x - WZo.x, WZo.y - Ze.y);
}
__device__ __forceinline__ void repack_pair(float2 Uk, float2 Ukk, float2 W,
                                            float2& zk, float2& zkk)
{
    float2 Eu = make_float2(0.5f*(Uk.x + Ukk.x), 0.5f*(Uk.y - Ukk.y));
    float2 D  = make_float2(0.5f*(Uk.x - Ukk.x), 0.5f*(Uk.y + Ukk.y));
    float2 Wc = make_float2(W.x, -W.y);
    float2 Ou = cmul(D, Wc);
    zk  = make_float2(Eu.x - Ou.y, Eu.y + Ou.x);
    zkk = make_float2(Eu.x + Ou.y, Ou.x - Eu.y);
}

// one spectral pair of the Toeplitz multiply (real transfer Ft)
__device__ __forceinline__ void pairB(int k, float2 Zk, float2 Zkk,
                                      const float* __restrict__ Ft,
                                      const float2* __restrict__ TW,
                                      float2& zk, float2& zkk)
{
    float2 t = TW[k];
    float2 W = make_float2(t.x, -t.y);
    float2 Bk, Bkk;
    unpack_pair(Zk, Zkk, W, Bk, Bkk);
    const float fk  = Ft[k];
    const float fkk = Ft[8192 - k];
    float2 Uk  = make_float2(Bk.x * fk,  Bk.y * fk);
    float2 Ukk = make_float2(Bkk.x * fkk, Bkk.y * fkk);
    repack_pair(Uk, Ukk, W, zk, zkk);
}

// fused: final radix-2 of fwd CFFT_8192 + specB. Reads A (post 3 r16 rounds),
// writes repacked spectrum to B. Item j owns butterflies j and 4096-j, which
// produce exactly spectral pairs (j, 8192-j) and (4096-j, 4096+j).
__device__ void r2_specB(const float2* __restrict__ A, float2* __restrict__ B,
                         const float* __restrict__ Ft, const float2* __restrict__ TW)
{
    for (int j = threadIdx.x; j <= 2048; j += BS) {
        float2 a0 = A[SW(j)], b0 = A[SW(j + 4096)];
        float2 Zj0 = make_float2(a0.x + b0.x, a0.y + b0.y);   // Z[j]
        float2 Zj1 = make_float2(a0.x - b0.x, a0.y - b0.y);   // Z[j+4096]
        if (j == 0) {
            float2 zk, zkk;
            pairB(0, Zj0, Zj0, Ft, TW, zk, zkk);
            B[SW(0)] = zk;
            pairB(4096, Zj1, Zj1, Ft, TW, zk, zkk);
            B[SW(4096)] = zk;
        } else if (j == 2048) {
            float2 zk, zkk;
            pairB(2048, Zj0, Zj1, Ft, TW, zk, zkk);
            B[SW(2048)] = zk;
            B[SW(6144)] = zkk;
        } else {
            float2 a1 = A[SW(4096 - j)], b1 = A[SW(8192 - j)];
            float2 Zm0 = make_float2(a1.x + b1.x, a1.y + b1.y); // Z[4096-j]
            float2 Zm1 = make_float2(a1.x - b1.x, a1.y - b1.y); // Z[8192-j]
            float2 zk, zkk;
            pairB(j, Zj0, Zm1, Ft, TW, zk, zkk);
            B[SW(j)]        = zk;
            B[SW(8192 - j)] = zkk;
            pairB(4096 - j, Zm0, Zj1, Ft, TW, zk, zkk);
            B[SW(4096 - j)] = zk;
            B[SW(4096 + j)] = zkk;
        }
    }
}

__device__ float block_reduce_sum(float v, float* red)
{
    __syncthreads();
    #pragma unroll
    for (int o = 16; o; o >>= 1) v += __shfl_down_sync(0xffffffffu, v, o);
    if ((threadIdx.x & 31) == 0) red[threadIdx.x >> 5] = v;
    __syncthreads();
    if (threadIdx.x < 32) {
        float t = (threadIdx.x < 16) ? red[threadIdx.x] : 0.0f;
        #pragma unroll
        for (int o = 8; o; o >>= 1) t += __shfl_down_sync(0xffffffffu, t, o);
        if (threadIdx.x == 0) red[0] = t;
    }
    __syncthreads();
    return red[0];
}

// Fused unpack * Fc * repack, in place on Z[0..4095] (Nh=4096, N=8192).
__device__ void specA(float2* Z, const float2* __restrict__ Fc,
                      const float2* __restrict__ TW)
{
    for (int k = threadIdx.x; k <= 2048; k += BS) {
        const int kk = (4096 - k) & 4095;
        float2 t = TW[k << 1];
        float2 W = make_float2(t.x, -t.y);
        float2 Bk, Bkk;
        unpack_pair(Z[SW(k)], Z[SW(kk)], W, Bk, Bkk);
        float2 Uk  = cmul(Bk,  Fc[k]);
        float2 Ukk = cmul(Bkk, Fc[4096 - k]);
        float2 zk, zkk;
        repack_pair(Uk, Ukk, W, zk, zkk);
        Z[SW(k)] = zk;
        if (k != 0) Z[SW(kk)] = zkk;
    }
}

__global__ void __launch_bounds__(BS)
power_kernel(const float* __restrict__ gx, const float* __restrict__ gc,
             const float* __restrict__ gb0)
{
    extern __shared__ float2 smem2[];
    float2* buf0 = smem2;               // 8192
    float2* buf1 = smem2 + 8192;        // 8192
    float2* Fc   = smem2 + 16384;       // 4097
    float2* TW   = smem2 + 20481;       // 4097 : (cos,sin)(2*pi*r/16384)
    float*  Ft   = (float*)(smem2 + 24578); // 8194
    float*  red  = Ft + 8194;           // 32

    const int tid = threadIdx.x;
    const int row = blockIdx.x;
    const float* xr = gx  + (size_t)row * 8192;
    const float* cr = gc  + (size_t)row * 8192;
    const float* br = gb0 + (size_t)row * 8192;

    // ---- twiddle table ----
    for (int r = tid; r <= 4096; r += BS) {
        float sv, cv;
        sincospif((float)r * (1.0f / 8192.0f), &sv, &cv);
        TW[r] = make_float2(cv, sv);
    }
    __syncthreads();

    // ---- Fc = DFT_8192(circ) / 4096 (half spectrum) ----
    for (int n = tid; n < 4096; n += BS)
        buf0[SW(n)] = make_float2(cr[2*n], cr[2*n + 1]);
    __syncthreads();
    r16_round<-1,12,0,false>(buf0, buf1, TW); __syncthreads();
    r16_round<-1,12,1,false>(buf1, buf0, TW); __syncthreads();
    r16_round<-1,12,2,false>(buf0, buf1, TW); __syncthreads();
    {
        float2* Z = buf1;
        const float sc = 1.0f / 4096.0f;
        for (int k = tid; k <= 2048; k += BS) {
            const int kk = (4096 - k) & 4095;
            float2 t = TW[k << 1];
            float2 W = make_float2(t.x, -t.y);
            float2 Bk, Bkk;
            unpack_pair(Z[SW(k)], Z[SW(kk)], W, Bk, Bkk);
            Fc[k]        = make_float2(Bk.x * sc,  Bk.y * sc);
            Fc[4096 - k] = make_float2(Bkk.x * sc, Bkk.y * sc);
        }
    }
    __syncthreads();

    // ---- Ft = Re(DFT_16384([x, 0, flip(x[1:])])) / 8192 (real half spectrum) ----
    for (int n = tid; n < 8192; n += BS) {
        const int j0 = 2*n, j1 = 2*n + 1;
        float e0 = (j0 < 8192) ? xr[j0] : ((j0 == 8192) ? 0.0f : xr[16384 - j0]);
        float e1 = (j1 < 8192) ? xr[j1] : xr[16384 - j1];
        buf0[SW(n)] = make_float2(e0, e1);
    }
    __syncthreads();
    r16_round<-1,13,0,false>(buf0, buf1, TW); __syncthreads();
    r16_round<-1,13,1,false>(buf1, buf0, TW); __syncthreads();
    r16_round<-1,13,2,false>(buf0, buf1, TW); __syncthreads();
    r2_full(buf1, buf0);                      __syncthreads();
    {
        float2* Z = buf0;
        const float sc = 1.0f / 8192.0f;
        for (int k = tid; k <= 4096; k += BS) {
            const int kk = (8192 - k) & 8191;
            float2 t = TW[k];
            float2 W = make_float2(t.x, -t.y);
            float2 Bk, Bkk;
            unpack_pair(Z[SW(k)], Z[SW(kk)], W, Bk, Bkk);
            Ft[k]        = Bk.x * sc;
            Ft[8192 - k] = Bkk.x * sc;
        }
    }
    __syncthreads();

    // ---- b = b0 / ||b0||, thread t owns b[16t .. 16t+15] ----
    float b[16];
    {
        #pragma unroll
        for (int q4 = 0; q4 < 4; q4++) {
            const float4 v = *(const float4*)(br + tid*16 + q4*4);
            b[q4*4+0] = v.x; b[q4*4+1] = v.y; b[q4*4+2] = v.z; b[q4*4+3] = v.w;
        }
        float ss = 0.0f;
        #pragma unroll
        for (int i = 0; i < 16; i++) ss += b[i]*b[i];
        float tot = block_reduce_sum(ss, red);
        float inv = 1.0f / sqrtf(tot);
        #pragma unroll
        for (int i = 0; i < 16; i++) b[i] *= inv;
    }

    // ---- 100 power iterations + 1 final application ----
    for (int it = 0; it <= 100; ++it) {
        // pack b: buf0[n] = (b[2n], b[2n+1]), n = 8*tid + j
        #pragma unroll
        for (int j = 0; j < 8; ++j)
            buf0[SW(8*tid + j)] = make_float2(b[2*j], b[2*j + 1]);
        __syncthreads();

        // u = IFFT( Fc * FFT(b) )   (8192-pt real conv via 4096-pt CFFT)
        r16_round<-1,12,0,false>(buf0, buf1, TW); __syncthreads();
        r16_round<-1,12,1,false>(buf1, buf0, TW); __syncthreads();
        r16_round<-1,12,2,false>(buf0, buf1, TW); __syncthreads();
        specA(buf1, Fc, TW);                      __syncthreads();
        r16_round<+1,12,0,false>(buf1, buf0, TW); __syncthreads();
        r16_round<+1,12,1,false>(buf0, buf1, TW); __syncthreads();
        r16_round<+1,12,2,false>(buf1, buf0, TW); __syncthreads();
        // buf0 now holds packed u; upper 4096 treated as zero via ZHI.

        // w = first 8192 of IFFT_16384( Ft * FFT_16384([u,0]) )
        r16_round<-1,13,0,true >(buf0, buf1, TW); __syncthreads();
        r16_round<-1,13,1,false>(buf1, buf0, TW); __syncthreads();
        r16_round<-1,13,2,false>(buf0, buf1, TW); __syncthreads();
        r2_specB(buf1, buf0, Ft, TW);             __syncthreads();
        r16_round<+1,13,0,false>(buf0, buf1, TW); __syncthreads();
        r16_round<+1,13,1,false>(buf1, buf0, TW); __syncthreads();
        r16_round<+1,13,2,false>(buf0, buf1, TW); __syncthreads();

        // final radix-2 straight into registers: w[n], n = 16t..16t+15
        float w_[16];
        #pragma unroll
        for (int j = 0; j < 8; ++j) {
            const int id = 8*tid + j;
            float2 a = buf1[SW(id)], bb2 = buf1[SW(id + 4096)];
            w_[2*j]     = a.x + bb2.x;
            w_[2*j + 1] = a.y + bb2.y;
        }

        if (it < 100) {
            float nb[16];
            float ss = 0.0f;
            #pragma unroll
            for (int i = 0; i < 16; i++) { nb[i] = b[i] - w_[i]; ss += nb[i]*nb[i]; }
            float tot = block_reduce_sum(ss, red);
            float inv = 1.0f / sqrtf(tot);
            #pragma unroll
            for (int i = 0; i < 16; i++) b[i] = nb[i] * inv;
        } else {
            float dp = 0.0f;
            #pragma unroll
            for (int i = 0; i < 16; i++) dp += b[i] * w_[i];
            float tot = block_reduce_sum(dp, red);
            if (tid == 0) g_sigma[row] = 1.0f - tot;   // sigma = b.(b-w) = 1 - b.w
        }
    }
}

__global__ void finalize_kernel(float* __restrict__ out)
{
    __shared__ float red[16];
    const int t = threadIdx.x;   // 512 threads
    float v = fabsf(g_sigma[t]);
    #pragma unroll
    for (int o = 16; o; o >>= 1) v += __shfl_down_sync(0xffffffffu, v, o);
    if ((t & 31) == 0) red[t >> 5] = v;
    __syncthreads();
    if (t < 16) {
        float s = red[t];
        #pragma unroll
        for (int o = 8; o; o >>= 1) s += __shfl_down_sync(0xffffu, s, o);
        if (t == 0) out[0] = s * (1.0f / 512.0f);
    }
}

extern "C" void kernel_launch(void* const* d_in, const int* in_sizes, int n_in,
                              void* d_out, int out_size)
{
    (void)in_sizes; (void)n_in; (void)out_size;
    const float* x    = (const float*)d_in[0];
    const float* circ = (const float*)d_in[1];
    const float* b0   = (const float*)d_in[2];

    cudaFuncSetAttribute(power_kernel,
                         cudaFuncAttributeMaxDynamicSharedMemorySize, SMEM_BYTES);
    power_kernel<<<NROW, BS, SMEM_BYTES>>>(x, circ, b0);
    finalize_kernel<<<1, 512>>>((float*)d_out);
}

// round 8
// speedup vs baseline: 1.0808x; 1.0430x over previous
#include <cuda_runtime.h>
#include <math.h>

#define BS   512
#define NROW 512
// smem: buf0(8192 c) + buf1(8192 c) + Fc(4097 c) + TW(4097 c) + Ft(8194 f) + red(32 f)
#define SMEM_BYTES (24578*8 + 8226*4)

typedef unsigned long long u64c;

__device__ float g_sigma[NROW];

// 8-byte-granularity bank swizzle: conflict unit for LDS.64 is the bank PAIR
// (16 per half-warp phase), so the key is index mod 16.
__device__ __forceinline__ int SW(int i) { return i ^ ((i >> 4) & 15); }

// ---------------- packed f32x2 primitives (sm_103a) ----------------
__device__ __forceinline__ u64c pk(float x, float y) {
    u64c r; asm("mov.b64 %0,{%1,%2};" : "=l"(r) : "f"(x), "f"(y)); return r;
}
__device__ __forceinline__ void unpk(u64c a, float& x, float& y) {
    asm("mov.b64 {%0,%1},%2;" : "=f"(x), "=f"(y) : "l"(a));
}
__device__ __forceinline__ u64c add2(u64c a, u64c b) {
    u64c r; asm("add.rn.f32x2 %0,%1,%2;" : "=l"(r) : "l"(a), "l"(b)); return r;
}
__device__ __forceinline__ u64c mul2(u64c a, u64c b) {
    u64c r; asm("mul.rn.f32x2 %0,%1,%2;" : "=l"(r) : "l"(a), "l"(b)); return r;
}
__device__ __forceinline__ u64c fma2(u64c a, u64c b, u64c c) {
    u64c r; asm("fma.rn.f32x2 %0,%1,%2,%3;" : "=l"(r) : "l"(a), "l"(b), "l"(c)); return r;
}
__device__ __forceinline__ u64c sub2(u64c a, u64c b) { return fma2(b, pk(-1.f, -1.f), a); }
__device__ __forceinline__ u64c swp(u64c a) { float x, y; unpk(a, x, y); return pk(y, x); }

__device__ __forceinline__ float2 cmul(float2 a, float2 b) {
    return make_float2(a.x*b.x - a.y*b.y, a.x*b.y + a.y*b.x);
}
// scalar complex w times packed complex v
__device__ __forceinline__ u64c cmulps(float2 w, u64c v) {
    float vx, vy; unpk(v, vx, vy);
    return pk(fmaf(w.x, vx, -w.y * vy), fmaf(w.x, vy, w.y * vx));
}
// packed v times constant twiddle (c, ds): (c*vx - ds*vy, c*vy + ds*vx)
__device__ __forceinline__ u64c ct(u64c v, float c, float ds) {
    return fma2(swp(v), pk(-ds, ds), mul2(pk(c, c), v));
}

// swizzled twiddle load (table stored at SW-permuted indices)
__device__ __forceinline__ float2 twl(const float2* __restrict__ TW, int i) {
    return TW[SW(i)];
}

// ---------------- packed radix-4 ----------------
template<int DIR>
__device__ __forceinline__ void dft4p(u64c& a, u64c& b, u64c& c, u64c& d) {
    u64c apc = add2(a, c), amc = sub2(a, c);
    u64c bpd = add2(b, d), bmd = sub2(b, d);
    a = add2(apc, bpd);
    c = sub2(apc, bpd);
    u64c s = swp(bmd);
    const float D = (DIR > 0) ? 1.f : -1.f;
    b = fma2(s, pk(-D, D), amc);   // amc + i*D*bmd
    d = fma2(s, pk(D, -D), amc);   // amc - i*D*bmd
}
// radix-4 with c=d=0 (fused zero-pad): out of (a,b,0,0)
template<int DIR>
__device__ __forceinline__ void dft4pz(u64c a, u64c b,
                                       u64c& o0, u64c& o1, u64c& o2, u64c& o3) {
    const float D = (DIR > 0) ? 1.f : -1.f;
    u64c s = swp(b);
    o0 = add2(a, b);
    o2 = sub2(a, b);
    o1 = fma2(s, pk(-D, D), a);
    o3 = fma2(s, pk(D, -D), a);
}

template<int DIR>
__device__ __forceinline__ void applyW16p(u64c* v) {
    const float C1 = 0.9238795325112867f, S1 = 0.3826834323650898f;
    const float H  = 0.7071067811865476f;
    const float D  = (DIR > 0) ? 1.f : -1.f;
    v[5]  = ct(v[5],  C1,  D*S1);
    v[9]  = ct(v[9],   H,  D*H);
    v[13] = ct(v[13], S1,  D*C1);
    v[6]  = ct(v[6],   H,  D*H);
    v[10] = mul2(swp(v[10]), pk(-D, D));   // * (0, D)
    v[14] = ct(v[14], -H,  D*H);
    v[7]  = ct(v[7],  S1,  D*C1);
    v[11] = ct(v[11], -H,  D*H);
    v[15] = ct(v[15], -C1, -D*S1);
}

// ---------------- one radix-16 Stockham round (compile-time shape) ----------------
template<int DIR, int LGS, int R, bool ZHI>
__device__ __forceinline__ void r16_round(const float2* __restrict__ xf,
                                          float2* __restrict__ yf,
                                          const float2* __restrict__ TW)
{
    constexpr int NBF   = 1 << (LGS - 4);
    constexpr int LS    = 4 * R;
    constexpr int S     = 1 << LS;
    constexpr int SHIFT = 14 - (LGS - LS);
    const u64c* x = (const u64c*)xf;
    u64c*       y = (u64c*)yf;
    const int id = threadIdx.x;
    if (NBF < BS && id >= NBF) return;
    const int q  = id & (S - 1);
    const int p  = id >> LS;
    const int ib = q + (p << LS);

    u64c v[16];
    if (ZHI) {
        #pragma unroll
        for (int r = 0; r < 8; r++) v[r] = x[SW(ib + r * NBF)];
        #pragma unroll
        for (int bb = 0; bb < 4; bb++)
            dft4pz<DIR>(v[bb], v[bb+4], v[bb], v[bb+4], v[bb+8], v[bb+12]);
    } else {
        #pragma unroll
        for (int r = 0; r < 16; r++) v[r] = x[SW(ib + r * NBF)];
        #pragma unroll
        for (int bb = 0; bb < 4; bb++)
            dft4p<DIR>(v[bb], v[bb+4], v[bb+8], v[bb+12]);
    }
    applyW16p<DIR>(v);
    #pragma unroll
    for (int c = 0; c < 4; c++)
        dft4p<DIR>(v[4*c], v[4*c+1], v[4*c+2], v[4*c+3]);

    const int ob = q + ((p << 4) << LS);
    if (R == 2 && p == 0) {
        // all stage twiddles are 1 (out j = c+4d from slot v[4c+d])
        y[SW(ob       )] = v[0];  y[SW(ob +    S)] = v[4];
        y[SW(ob +  2*S)] = v[8];  y[SW(ob +  3*S)] = v[12];
        y[SW(ob +  4*S)] = v[1];  y[SW(ob +  5*S)] = v[5];
        y[SW(ob +  6*S)] = v[9];  y[SW(ob +  7*S)] = v[13];
        y[SW(ob +  8*S)] = v[2];  y[SW(ob +  9*S)] = v[6];
        y[SW(ob + 10*S)] = v[10]; y[SW(ob + 11*S)] = v[14];
        y[SW(ob + 12*S)] = v[3];  y[SW(ob + 13*S)] = v[7];
        y[SW(ob + 14*S)] = v[11]; y[SW(ob + 15*S)] = v[15];
    } else {
        float2 t  = twl(TW, p << SHIFT);
        float2 w1 = make_float2(t.x, (DIR > 0) ? t.y : -t.y);
        float2 w2 = cmul(w1, w1);
        float2 w3 = cmul(w2, w1);
        float2 w4 = cmul(w2, w2);
        y[SW(ob       )] = v[0];
        y[SW(ob +    S)] = cmulps(w1, v[4]);
        y[SW(ob +  2*S)] = cmulps(w2, v[8]);
        y[SW(ob +  3*S)] = cmulps(w3, v[12]);
        float2 wr = w4;
        #pragma unroll
        for (int d = 1; d < 4; d++) {
            const int jb = 4 * d;
            y[SW(ob + (jb    )*S)] = cmulps(wr, v[d]);
            y[SW(ob + (jb + 1)*S)] = cmulps(cmul(wr, w1), v[4 + d]);
            y[SW(ob + (jb + 2)*S)] = cmulps(cmul(wr, w2), v[8 + d]);
            y[SW(ob + (jb + 3)*S)] = cmulps(cmul(wr, w3), v[12 + d]);
            if (d < 3) wr = cmul(wr, w4);
        }
    }
}

// plain final radix-2 for the 8192 FFT (preamble only): B = r2(A)
__device__ void r2_full(const float2* __restrict__ A, float2* __restrict__ B)
{
    for (int id = threadIdx.x; id < 4096; id += BS) {
        float2 a = A[SW(id)], b = A[SW(id + 4096)];
        B[SW(id)]        = make_float2(a.x + b.x, a.y + b.y);
        B[SW(id + 4096)] = make_float2(a.x - b.x, a.y - b.y);
    }
}

// ---------------- real-FFT pack/unpack ----------------
__device__ __forceinline__ void unpack_pair(float2 Zk, float2 Zkk, float2 W,
                                            float2& Bk, float2& Bkk)
{
    float2 Ze  = make_float2(0.5f*(Zk.x + Zkk.x), 0.5f*(Zk.y - Zkk.y));
    float2 Zo  = make_float2(0.5f*(Zk.y + Zkk.y), -0.5f*(Zk.x - Zkk.x));
    float2 WZo = cmul(W, Zo);
    Bk  = make_float2(Ze.x + WZo.x, Ze.y + WZo.y);
    Bkk = make_float2(Ze.x - WZo.x, WZo.y - Ze.y);
}
__device__ __forceinline__ void repack_pair(float2 Uk, float2 Ukk, float2 W,
                                            float2& zk, float2& zkk)
{
    float2 Eu = make_float2(0.5f*(Uk.x + Ukk.x), 0.5f*(Uk.y - Ukk.y));
    float2 D  = make_float2(0.5f*(Uk.x - Ukk.x), 0.5f*(Uk.y + Ukk.y));
    float2 Wc = make_float2(W.x, -W.y);
    float2 Ou = cmul(D, Wc);
    zk  = make_float2(Eu.x - Ou.y, Eu.y + Ou.x);
    zkk = make_float2(Eu.x + Ou.y, Ou.x - Eu.y);
}

// one spectral pair of the Toeplitz multiply (real transfer Ft)
__device__ __forceinline__ void pairB(int k, float2 Zk, float2 Zkk,
                                      const float* __restrict__ Ft,
                                      const float2* __restrict__ TW,
                                      float2& zk, float2& zkk)
{
    float2 t = twl(TW, k);
    float2 W = make_float2(t.x, -t.y);
    float2 Bk, Bkk;
    unpack_pair(Zk, Zkk, W, Bk, Bkk);
    const float fk  = Ft[k];
    const float fkk = Ft[8192 - k];
    float2 Uk  = make_float2(Bk.x * fk,  Bk.y * fk);
    float2 Ukk = make_float2(Bkk.x * fkk, Bkk.y * fkk);
    repack_pair(Uk, Ukk, W, zk, zkk);
}

// fused: final radix-2 of fwd CFFT_8192 + specB. Reads A (post 3 r16 rounds),
// writes repacked spectrum to B. Item j owns butterflies j and 4096-j, which
// produce exactly spectral pairs (j, 8192-j) and (4096-j, 4096+j).
__device__ void r2_specB(const float2* __restrict__ A, float2* __restrict__ B,
                         const float* __restrict__ Ft, const float2* __restrict__ TW)
{
    for (int j = threadIdx.x; j <= 2048; j += BS) {
        float2 a0 = A[SW(j)], b0 = A[SW(j + 4096)];
        float2 Zj0 = make_float2(a0.x + b0.x, a0.y + b0.y);   // Z[j]
        float2 Zj1 = make_float2(a0.x - b0.x, a0.y - b0.y);   // Z[j+4096]
        if (j == 0) {
            float2 zk, zkk;
            pairB(0, Zj0, Zj0, Ft, TW, zk, zkk);
            B[SW(0)] = zk;
            pairB(4096, Zj1, Zj1, Ft, TW, zk, zkk);
            B[SW(4096)] = zk;
        } else if (j == 2048) {
            float2 zk, zkk;
            pairB(2048, Zj0, Zj1, Ft, TW, zk, zkk);
            B[SW(2048)] = zk;
            B[SW(6144)] = zkk;
        } else {
            float2 a1 = A[SW(4096 - j)], b1 = A[SW(8192 - j)];
            float2 Zm0 = make_float2(a1.x + b1.x, a1.y + b1.y); // Z[4096-j]
            float2 Zm1 = make_float2(a1.x - b1.x, a1.y - b1.y); // Z[8192-j]
            float2 zk, zkk;
            pairB(j, Zj0, Zm1, Ft, TW, zk, zkk);
            B[SW(j)]        = zk;
            B[SW(8192 - j)] = zkk;
            pairB(4096 - j, Zm0, Zj1, Ft, TW, zk, zkk);
            B[SW(4096 - j)] = zk;
            B[SW(4096 + j)] = zkk;
        }
    }
}

__device__ float block_reduce_sum(float v, float* red)
{
    __syncthreads();
    #pragma unroll
    for (int o = 16; o; o >>= 1) v += __shfl_down_sync(0xffffffffu, v, o);
    if ((threadIdx.x & 31) == 0) red[threadIdx.x >> 5] = v;
    __syncthreads();
    if (threadIdx.x < 32) {
        float t = (threadIdx.x < 16) ? red[threadIdx.x] : 0.0f;
        #pragma unroll
        for (int o = 8; o; o >>= 1) t += __shfl_down_sync(0xffffffffu, t, o);
        if (threadIdx.x == 0) red[0] = t;
    }
    __syncthreads();
    return red[0];
}

// Fused unpack * Fc * repack, in place on Z[0..4095] (Nh=4096, N=8192).
__device__ void specA(float2* Z, const float2* __restrict__ Fc,
                      const float2* __restrict__ TW)
{
    for (int k = threadIdx.x; k <= 2048; k += BS) {
        const int kk = (4096 - k) & 4095;
        float2 t = twl(TW, k << 1);
        float2 W = make_float2(t.x, -t.y);
        float2 Bk, Bkk;
        unpack_pair(Z[SW(k)], Z[SW(kk)], W, Bk, Bkk);
        float2 Uk  = cmul(Bk,  Fc[k]);
        float2 Ukk = cmul(Bkk, Fc[4096 - k]);
        float2 zk, zkk;
        repack_pair(Uk, Ukk, W, zk, zkk);
        Z[SW(k)] = zk;
        if (k != 0) Z[SW(kk)] = zkk;
    }
}

__global__ void __launch_bounds__(BS)
power_kernel(const float* __restrict__ gx, const float* __restrict__ gc,
             const float* __restrict__ gb0)
{
    extern __shared__ float2 smem2[];
    float2* buf0 = smem2;               // 8192
    float2* buf1 = smem2 + 8192;        // 8192
    float2* Fc   = smem2 + 16384;       // 4097
    float2* TW   = smem2 + 20481;       // 4097 : (cos,sin)(2*pi*r/16384), SW-permuted
    float*  Ft   = (float*)(smem2 + 24578); // 8194
    float*  red  = Ft + 8194;           // 32

    const int tid = threadIdx.x;
    const int row = blockIdx.x;
    const float* xr = gx  + (size_t)row * 8192;
    const float* cr = gc  + (size_t)row * 8192;
    const float* br = gb0 + (size_t)row * 8192;

    // ---- twiddle table (stored swizzled) ----
    for (int r = tid; r <= 4096; r += BS) {
        float sv, cv;
        sincospif((float)r * (1.0f / 8192.0f), &sv, &cv);
        TW[SW(r)] = make_float2(cv, sv);
    }
    __syncthreads();

    // ---- Fc = DFT_8192(circ) / 4096 (half spectrum) ----
    for (int n = tid; n < 4096; n += BS)
        buf0[SW(n)] = make_float2(cr[2*n], cr[2*n + 1]);
    __syncthreads();
    r16_round<-1,12,0,false>(buf0, buf1, TW); __syncthreads();
    r16_round<-1,12,1,false>(buf1, buf0, TW); __syncthreads();
    r16_round<-1,12,2,false>(buf0, buf1, TW); __syncthreads();
    {
        float2* Z = buf1;
        const float sc = 1.0f / 4096.0f;
        for (int k = tid; k <= 2048; k += BS) {
            const int kk = (4096 - k) & 4095;
            float2 t = twl(TW, k << 1);
            float2 W = make_float2(t.x, -t.y);
            float2 Bk, Bkk;
            unpack_pair(Z[SW(k)], Z[SW(kk)], W, Bk, Bkk);
            Fc[k]        = make_float2(Bk.x * sc,  Bk.y * sc);
            Fc[4096 - k] = make_float2(Bkk.x * sc, Bkk.y * sc);
        }
    }
    __syncthreads();

    // ---- Ft = Re(DFT_16384([x, 0, flip(x[1:])])) / 8192 (real half spectrum) ----
    for (int n = tid; n < 8192; n += BS) {
        const int j0 = 2*n, j1 = 2*n + 1;
        float e0 = (j0 < 8192) ? xr[j0] : ((j0 == 8192) ? 0.0f : xr[16384 - j0]);
        float e1 = (j1 < 8192) ? xr[j1] : xr[16384 - j1];
        buf0[SW(n)] = make_float2(e0, e1);
    }
    __syncthreads();
    r16_round<-1,13,0,false>(buf0, buf1, TW); __syncthreads();
    r16_round<-1,13,1,false>(buf1, buf0, TW); __syncthreads();
    r16_round<-1,13,2,false>(buf0, buf1, TW); __syncthreads();
    r2_full(buf1, buf0);                      __syncthreads();
    {
        float2* Z = buf0;
        const float sc = 1.0f / 8192.0f;
        for (int k = tid; k <= 4096; k += BS) {
            const int kk = (8192 - k) & 8191;
            float2 t = twl(TW, k);
            float2 W = make_float2(t.x, -t.y);
            float2 Bk, Bkk;
            unpack_pair(Z[SW(k)], Z[SW(kk)], W, Bk, Bkk);
            Ft[k]        = Bk.x * sc;
            Ft[8192 - k] = Bkk.x * sc;
        }
    }
    __syncthreads();

    // ---- b = b0 / ||b0||, thread t owns b[16t .. 16t+15] ----
    float b[16];
    {
        #pragma unroll
        for (int q4 = 0; q4 < 4; q4++) {
            const float4 v = *(const float4*)(br + tid*16 + q4*4);
            b[q4*4+0] = v.x; b[q4*4+1] = v.y; b[q4*4+2] = v.z; b[q4*4+3] = v.w;
        }
        float ss = 0.0f;
        #pragma unroll
        for (int i = 0; i < 16; i++) ss += b[i]*b[i];
        float tot = block_reduce_sum(ss, red);
        float inv = 1.0f / sqrtf(tot);
        #pragma unroll
        for (int i = 0; i < 16; i++) b[i] *= inv;
    }

    // ---- 100 power iterations + 1 final application (exact early-exit) ----
    for (int it = 0; it <= 100; ++it) {
        // pack b: buf0[n] = (b[2n], b[2n+1]), n = 8*tid + j
        #pragma unroll
        for (int j = 0; j < 8; ++j)
            buf0[SW(8*tid + j)] = make_float2(b[2*j], b[2*j + 1]);
        __syncthreads();

        // u = IFFT( Fc * FFT(b) )   (8192-pt real conv via 4096-pt CFFT)
        r16_round<-1,12,0,false>(buf0, buf1, TW); __syncthreads();
        r16_round<-1,12,1,false>(buf1, buf0, TW); __syncthreads();
        r16_round<-1,12,2,false>(buf0, buf1, TW); __syncthreads();
        specA(buf1, Fc, TW);                      __syncthreads();
        r16_round<+1,12,0,false>(buf1, buf0, TW); __syncthreads();
        r16_round<+1,12,1,false>(buf0, buf1, TW); __syncthreads();
        r16_round<+1,12,2,false>(buf1, buf0, TW); __syncthreads();
        // buf0 now holds packed u; upper 4096 treated as zero via ZHI.

        // w = first 8192 of IFFT_16384( Ft * FFT_16384([u,0]) )
        r16_round<-1,13,0,true >(buf0, buf1, TW); __syncthreads();
        r16_round<-1,13,1,false>(buf1, buf0, TW); __syncthreads();
        r16_round<-1,13,2,false>(buf0, buf1, TW); __syncthreads();
        r2_specB(buf1, buf0, Ft, TW);             __syncthreads();
        r16_round<+1,13,0,false>(buf0, buf1, TW); __syncthreads();
        r16_round<+1,13,1,false>(buf1, buf0, TW); __syncthreads();
        r16_round<+1,13,2,false>(buf0, buf1, TW); __syncthreads();

        // final radix-2 straight into registers: w[n], n = 16t..16t+15
        float w_[16];
        #pragma unroll
        for (int j = 0; j < 8; ++j) {
            const int id = 8*tid + j;
            float2 a = buf1[SW(id)], bb2 = buf1[SW(id + 4096)];
            w_[2*j]     = a.x + bb2.x;
            w_[2*j + 1] = a.y + bb2.y;
        }

        if (it < 100) {
            float nb[16];
            float ss = 0.0f;
            #pragma unroll
            for (int i = 0; i < 16; i++) { nb[i] = b[i] - w_[i]; ss += nb[i]*nb[i]; }
            float tot = block_reduce_sum(ss, red);
            float inv = 1.0f / sqrtf(tot);
            int eqp = 1, eqn = 1;
            #pragma unroll
            for (int i = 0; i < 16; i++) {
                float nv = nb[i] * inv;
                eqp &= (nv ==  b[i]);
                eqn &= (nv == -b[i]);
                b[i] = nv;
            }
            // exact fixed point (period 1) or exact sign flip (period 2).
            // Either way the remaining trajectory is bit-identical up to a
            // global sign, and sigma = b.(b - Mb') is sign-invariant.
            eqp = __syncthreads_and(eqp);
            eqn = __syncthreads_and(eqn);
            if (eqp | eqn) it = 99;   // next pass is the final application
        } else {
            float dp = 0.0f;
            #pragma unroll
            for (int i = 0; i < 16; i++) dp += b[i] * w_[i];
            float tot = block_reduce_sum(dp, red);
            if (tid == 0) g_sigma[row] = 1.0f - tot;   // sigma = b.(b-w) = 1 - b.w
        }
    }
}

__global__ void finalize_kernel(float* __restrict__ out)
{
    __shared__ float red[16];
    const int t = threadIdx.x;   // 512 threads
    float v = fabsf(g_sigma[t]);
    #pragma unroll
    for (int o = 16; o; o >>= 1) v += __shfl_down_sync(0xffffffffu, v, o);
    if ((t & 31) == 0) red[t >> 5] = v;
    __syncthreads();
    if (t < 16) {
        float s = red[t];
        #pragma unroll
        for (int o = 8; o; o >>= 1) s += __shfl_down_sync(0xffffu, s, o);
        if (t == 0) out[0] = s * (1.0f / 512.0f);
    }
}

extern "C" void kernel_launch(void* const* d_in, const int* in_sizes, int n_in,
                              void* d_out, int out_size)
{
    (void)in_sizes; (void)n_in; (void)out_size;
    const float* x    = (const float*)d_in[0];
    const float* circ = (const float*)d_in[1];
    const float* b0   = (const float*)d_in[2];

    cudaFuncSetAttribute(power_kernel,
                         cudaFuncAttributeMaxDynamicSharedMemorySize, SMEM_BYTES);
    power_kernel<<<NROW, BS, SMEM_BYTES>>>(x, circ, b0);
    finalize_kernel<<<1, 512>>>((float*)d_out);
}

// round 9
// speedup vs baseline: 1.2266x; 1.1349x over previous
#include <cuda_runtime.h>
#include <math.h>

#define BS   512
#define NROW 512
// smem: buf0(8192 c) + buf1(8192 c) + Fc(4097 c) + TW(4097 c) + Ft(8194 f) + red(32 f)
#define SMEM_BYTES (24578*8 + 8226*4)

typedef unsigned long long u64c;

__device__ float g_sigma[NROW];

// 8-byte-granularity bank swizzle (LDS.64 conflict unit = bank pair, 16/phase)
__device__ __forceinline__ int SW(int i) { return i ^ ((i >> 4) & 15); }

// ---------------- packed f32x2 primitives (sm_103a) ----------------
__device__ __forceinline__ u64c pk(float x, float y) {
    u64c r; asm("mov.b64 %0,{%1,%2};" : "=l"(r) : "f"(x), "f"(y)); return r;
}
__device__ __forceinline__ void unpk(u64c a, float& x, float& y) {
    asm("mov.b64 {%0,%1},%2;" : "=f"(x), "=f"(y) : "l"(a));
}
__device__ __forceinline__ u64c add2(u64c a, u64c b) {
    u64c r; asm("add.rn.f32x2 %0,%1,%2;" : "=l"(r) : "l"(a), "l"(b)); return r;
}
__device__ __forceinline__ u64c mul2(u64c a, u64c b) {
    u64c r; asm("mul.rn.f32x2 %0,%1,%2;" : "=l"(r) : "l"(a), "l"(b)); return r;
}
__device__ __forceinline__ u64c fma2(u64c a, u64c b, u64c c) {
    u64c r; asm("fma.rn.f32x2 %0,%1,%2,%3;" : "=l"(r) : "l"(a), "l"(b), "l"(c)); return r;
}
__device__ __forceinline__ u64c sub2(u64c a, u64c b) { return fma2(b, pk(-1.f, -1.f), a); }
__device__ __forceinline__ u64c swp(u64c a) { float x, y; unpk(a, x, y); return pk(y, x); }

__device__ __forceinline__ float2 cmul(float2 a, float2 b) {
    return make_float2(a.x*b.x - a.y*b.y, a.x*b.y + a.y*b.x);
}
// scalar complex w times packed complex v
__device__ __forceinline__ u64c cmulps(float2 w, u64c v) {
    float vx, vy; unpk(v, vx, vy);
    return pk(fmaf(w.x, vx, -w.y * vy), fmaf(w.x, vy, w.y * vx));
}
// packed v times constant twiddle (c, ds)
__device__ __forceinline__ u64c ct(u64c v, float c, float ds) {
    return fma2(swp(v), pk(-ds, ds), mul2(pk(c, c), v));
}
// swizzled twiddle load (table stored SW-permuted). TW[r] = (cos,sin)(2*pi*r/16384)
__device__ __forceinline__ float2 twl(const float2* __restrict__ TW, int i) {
    return TW[SW(i)];
}

// ---------------- packed radix-4 ----------------
template<int DIR>
__device__ __forceinline__ void dft4p(u64c& a, u64c& b, u64c& c, u64c& d) {
    u64c apc = add2(a, c), amc = sub2(a, c);
    u64c bpd = add2(b, d), bmd = sub2(b, d);
    a = add2(apc, bpd);
    c = sub2(apc, bpd);
    u64c s = swp(bmd);
    const float D = (DIR > 0) ? 1.f : -1.f;
    b = fma2(s, pk(-D, D), amc);
    d = fma2(s, pk(D, -D), amc);
}

template<int DIR>
__device__ __forceinline__ void applyW16p(u64c* v) {
    const float C1 = 0.9238795325112867f, S1 = 0.3826834323650898f;
    const float H  = 0.7071067811865476f;
    const float D  = (DIR > 0) ? 1.f : -1.f;
    v[5]  = ct(v[5],  C1,  D*S1);
    v[9]  = ct(v[9],   H,  D*H);
    v[13] = ct(v[13], S1,  D*C1);
    v[6]  = ct(v[6],   H,  D*H);
    v[10] = mul2(swp(v[10]), pk(-D, D));
    v[14] = ct(v[14], -H,  D*H);
    v[7]  = ct(v[7],  S1,  D*C1);
    v[11] = ct(v[11], -H,  D*H);
    v[15] = ct(v[15], -C1, -D*S1);
}

// ---------------- scatter with stage twiddles (shared tail) ----------------
template<int DIR, int S>
__device__ __forceinline__ void r16_store(u64c* __restrict__ y, int ob, u64c* v,
                                          float2 t)
{
    float2 w1 = make_float2(t.x, (DIR > 0) ? t.y : -t.y);
    float2 w2 = cmul(w1, w1);
    float2 w3 = cmul(w2, w1);
    float2 w4 = cmul(w2, w2);
    y[SW(ob       )] = v[0];
    y[SW(ob +    S)] = cmulps(w1, v[4]);
    y[SW(ob +  2*S)] = cmulps(w2, v[8]);
    y[SW(ob +  3*S)] = cmulps(w3, v[12]);
    float2 wr = w4;
    #pragma unroll
    for (int d = 1; d < 4; d++) {
        const int jb = 4 * d;
        y[SW(ob + (jb    )*S)] = cmulps(wr, v[d]);
        y[SW(ob + (jb + 1)*S)] = cmulps(cmul(wr, w1), v[4 + d]);
        y[SW(ob + (jb + 2)*S)] = cmulps(cmul(wr, w2), v[8 + d]);
        y[SW(ob + (jb + 3)*S)] = cmulps(cmul(wr, w3), v[12 + d]);
        if (d < 3) wr = cmul(wr, w4);
    }
}
template<int S>
__device__ __forceinline__ void r16_store_triv(u64c* __restrict__ y, int ob, u64c* v)
{
    y[SW(ob       )] = v[0];  y[SW(ob +    S)] = v[4];
    y[SW(ob +  2*S)] = v[8];  y[SW(ob +  3*S)] = v[12];
    y[SW(ob +  4*S)] = v[1];  y[SW(ob +  5*S)] = v[5];
    y[SW(ob +  6*S)] = v[9];  y[SW(ob +  7*S)] = v[13];
    y[SW(ob +  8*S)] = v[2];  y[SW(ob +  9*S)] = v[6];
    y[SW(ob + 10*S)] = v[10]; y[SW(ob + 11*S)] = v[14];
    y[SW(ob + 12*S)] = v[3];  y[SW(ob + 13*S)] = v[7];
    y[SW(ob + 14*S)] = v[11]; y[SW(ob + 15*S)] = v[15];
}

// ---------------- 4096-pt radix-16 round body (id = 0..255) ----------------
// MOD (R0 only): input element j is multiplied by exp(-2*pi*i*j/8192) on load.
template<int DIR, int R, bool MOD>
__device__ __forceinline__ void r16_body12(const u64c* __restrict__ x,
                                           u64c* __restrict__ y, int id,
                                           const float2* __restrict__ TW)
{
    constexpr int NBF   = 256;
    constexpr int LS    = 4 * R;
    constexpr int S     = 1 << LS;
    constexpr int SHIFT = 2 + LS;
    const int q  = id & (S - 1);
    const int p  = id >> LS;
    const int ib = q + (p << LS);

    u64c v[16];
    #pragma unroll
    for (int r = 0; r < 16; r++) v[r] = x[SW(ib + r * NBF)];

    if (MOD) {
        float2 t0 = twl(TW, 2 * id);
        float2 w  = make_float2(t0.x, -t0.y);   // exp(-2*pi*i*id/8192)
        const float2 CM = make_float2(0.980785280403230449f,
                                     -0.195090322016128268f); // exp(-i*pi/16)
        #pragma unroll
        for (int r = 0; r < 16; r++) {
            v[r] = cmulps(w, v[r]);
            w = cmul(w, CM);
        }
    }

    #pragma unroll
    for (int bb = 0; bb < 4; bb++)
        dft4p<DIR>(v[bb], v[bb+4], v[bb+8], v[bb+12]);
    applyW16p<DIR>(v);
    #pragma unroll
    for (int c = 0; c < 4; c++)
        dft4p<DIR>(v[4*c], v[4*c+1], v[4*c+2], v[4*c+3]);

    const int ob = q + ((p << 4) << LS);
    if (R == 2) {
        r16_store_triv<S>(y, ob, v);            // p == 0 always at R2
    } else {
        r16_store<DIR, S>(y, ob, v, twl(TW, p << SHIFT));
    }
}

// single 4096 FFT pass (threads 0..255)
template<int DIR, int R, bool MOD>
__device__ __forceinline__ void r16_s(const float2* x, float2* y,
                                      const float2* TW)
{
    if (threadIdx.x < 256)
        r16_body12<DIR, R, MOD>((const u64c*)x, (u64c*)y, threadIdx.x, TW);
}
// dual concurrent inverse 4096 FFT pass (even: threads 0-255, odd: 256-511)
template<int R>
__device__ __forceinline__ void r16_dual(const float2* xe, float2* ye,
                                         const float2* xo, float2* yo,
                                         const float2* TW)
{
    const int id = threadIdx.x & 255;
    if (threadIdx.x < 256)
        r16_body12<+1, R, false>((const u64c*)xe, (u64c*)ye, id, TW);
    else
        r16_body12<+1, R, false>((const u64c*)xo, (u64c*)yo, id, TW);
}

// ---------------- 8192-pt radix-16 round (preamble only, 512 threads) ----------------
template<int DIR, int R>
__device__ __forceinline__ void r16_round13(const float2* __restrict__ xf,
                                            float2* __restrict__ yf,
                                            const float2* __restrict__ TW)
{
    constexpr int NBF   = 512;
    constexpr int LS    = 4 * R;
    constexpr int S     = 1 << LS;
    constexpr int SHIFT = 1 + LS;
    const u64c* x = (const u64c*)xf;
    u64c*       y = (u64c*)yf;
    const int id = threadIdx.x;
    const int q  = id & (S - 1);
    const int p  = id >> LS;
    const int ib = q + (p << LS);

    u64c v[16];
    #pragma unroll
    for (int r = 0; r < 16; r++) v[r] = x[SW(ib + r * NBF)];
    #pragma unroll
    for (int bb = 0; bb < 4; bb++)
        dft4p<DIR>(v[bb], v[bb+4], v[bb+8], v[bb+12]);
    applyW16p<DIR>(v);
    #pragma unroll
    for (int c = 0; c < 4; c++)
        dft4p<DIR>(v[4*c], v[4*c+1], v[4*c+2], v[4*c+3]);

    const int ob = q + ((p << 4) << LS);
    if (R == 2 && p == 0) r16_store_triv<S>(y, ob, v);
    else                  r16_store<DIR, S>(y, ob, v, twl(TW, p << SHIFT));
}

// preamble final radix-2 for the 8192 FFT
__device__ void r2_full(const float2* __restrict__ A, float2* __restrict__ B)
{
    for (int id = threadIdx.x; id < 4096; id += BS) {
        float2 a = A[SW(id)], b = A[SW(id + 4096)];
        B[SW(id)]        = make_float2(a.x + b.x, a.y + b.y);
        B[SW(id + 4096)] = make_float2(a.x - b.x, a.y - b.y);
    }
}

// ---------------- real-FFT pack/unpack ----------------
__device__ __forceinline__ void unpack_pair(float2 Zk, float2 Zkk, float2 W,
                                            float2& Bk, float2& Bkk)
{
    float2 Ze  = make_float2(0.5f*(Zk.x + Zkk.x), 0.5f*(Zk.y - Zkk.y));
    float2 Zo  = make_float2(0.5f*(Zk.y + Zkk.y), -0.5f*(Zk.x - Zkk.x));
    float2 WZo = cmul(W, Zo);
    Bk  = make_float2(Ze.x + WZo.x, Ze.y + WZo.y);
    Bkk = make_float2(Ze.x - WZo.x, WZo.y - Ze.y);
}
__device__ __forceinline__ void repack_pair(float2 Uk, float2 Ukk, float2 W,
                                            float2& zk, float2& zkk)
{
    float2 Eu = make_float2(0.5f*(Uk.x + Ukk.x), 0.5f*(Uk.y - Ukk.y));
    float2 D  = make_float2(0.5f*(Uk.x - Ukk.x), 0.5f*(Uk.y + Ukk.y));
    float2 Wc = make_float2(W.x, -W.y);
    float2 Ou = cmul(D, Wc);
    zk  = make_float2(Eu.x - Ou.y, Eu.y + Ou.x);
    zkk = make_float2(Eu.x + Ou.y, Ou.x - Eu.y);
}

__device__ float block_reduce_sum(float v, float* red)
{
    __syncthreads();
    #pragma unroll
    for (int o = 16; o; o >>= 1) v += __shfl_down_sync(0xffffffffu, v, o);
    if ((threadIdx.x & 31) == 0) red[threadIdx.x >> 5] = v;
    __syncthreads();
    if (threadIdx.x < 32) {
        float t = (threadIdx.x < 16) ? red[threadIdx.x] : 0.0f;
        #pragma unroll
        for (int o = 8; o; o >>= 1) t += __shfl_down_sync(0xffffffffu, t, o);
        if (threadIdx.x == 0) red[0] = t;
    }
    __syncthreads();
    return red[0];
}

// Fused unpack * Fc * repack, in place (pairs (k, 4096-k)), 512 threads.
__device__ void specA(float2* Z, const float2* __restrict__ Fc,
                      const float2* __restrict__ TW)
{
    for (int k = threadIdx.x; k <= 2048; k += BS) {
        const int kk = (4096 - k) & 4095;
        float2 t = twl(TW, k << 1);
        float2 W = make_float2(t.x, -t.y);
        float2 Bk, Bkk;
        unpack_pair(Z[SW(k)], Z[SW(kk)], W, Bk, Bkk);
        float2 Uk  = cmul(Bk,  Fc[k]);
        float2 Ukk = cmul(Bkk, Fc[4096 - k]);
        float2 zk, zkk;
        repack_pair(Uk, Ukk, W, zk, zkk);
        Z[SW(k)] = zk;
        if (k != 0) Z[SW(kk)] = zkk;
    }
}

// one spectral pair of the Toeplitz multiply at 16384-domain index k
__device__ __forceinline__ void pairB(int k, float2 Zk, float2 Zkk, float scale,
                                      const float* __restrict__ Ft,
                                      const float2* __restrict__ TW,
                                      float2& zk, float2& zkk)
{
    float2 t = twl(TW, k);
    float2 W = make_float2(t.x, -t.y);
    float2 Bk, Bkk;
    unpack_pair(Zk, Zkk, W, Bk, Bkk);
    const float fk  = Ft[k] * scale;
    const float fkk = Ft[8192 - k] * scale;
    float2 Uk  = make_float2(Bk.x * fk,  Bk.y * fk);
    float2 Ukk = make_float2(Bkk.x * fkk, Bkk.y * fkk);
    repack_pair(Uk, Ukk, W, zk, zkk);
}

// Dual-branch specB in ONE pass.
//  even branch (threads 0-255): Z2[2m] = 4096*Zp[m] (Zp = specA output, kept).
//    reads Zp pairs (m, (4096-m)&4095), writes repacked even spectrum to De.
//  odd branch (threads 256-511): Z2[2m+1] = Vo[m] (modulated FFT output).
//    pairs (m, 4095-m), in-place on Vo.
__device__ void spec_dual(const float2* __restrict__ Zp, float2* __restrict__ De,
                          float2* __restrict__ Vo,
                          const float* __restrict__ Ft,
                          const float2* __restrict__ TW)
{
    const int t = threadIdx.x;
    if (t < 256) {
        for (int m = t; m <= 2048; m += 256) {
            const int mm = (4096 - m) & 4095;
            float2 zk, zkk;
            pairB(2 * m, Zp[SW(m)], Zp[SW(mm)], 4096.f, Ft, TW, zk, zkk);
            De[SW(m)] = zk;
            if (m != 0 && m != 2048) De[SW(mm)] = zkk;
        }
    } else {
        for (int m = t - 256; m < 2048; m += 256) {
            const int mm = 4095 - m;
            float2 zk, zkk;
            float2 a = Vo[SW(m)], b = Vo[SW(mm)];
            pairB(2 * m + 1, a, b, 1.f, Ft, TW, zk, zkk);
            Vo[SW(m)]  = zk;
            Vo[SW(mm)] = zkk;
        }
    }
}

__global__ void __launch_bounds__(BS)
power_kernel(const float* __restrict__ gx, const float* __restrict__ gc,
             const float* __restrict__ gb0)
{
    extern __shared__ float2 smem2[];
    float2* Abuf = smem2;               // 4096
    float2* Bbuf = smem2 + 4096;        // 4096
    float2* Cbuf = smem2 + 8192;        // 4096
    float2* Dbuf = smem2 + 12288;       // 4096
    float2* Fc   = smem2 + 16384;       // 4097
    float2* TW   = smem2 + 20481;       // 4097 (SW-permuted)
    float*  Ft   = (float*)(smem2 + 24578); // 8194
    float*  red  = Ft + 8194;           // 32

    const int tid = threadIdx.x;
    const int row = blockIdx.x;
    const float* xr = gx  + (size_t)row * 8192;
    const float* cr = gc  + (size_t)row * 8192;
    const float* br = gb0 + (size_t)row * 8192;

    // ---- twiddle table (stored swizzled) ----
    for (int r = tid; r <= 4096; r += BS) {
        float sv, cv;
        sincospif((float)r * (1.0f / 8192.0f), &sv, &cv);
        TW[SW(r)] = make_float2(cv, sv);
    }
    __syncthreads();

    // ---- Fc = DFT_8192(circ) / 4096 (half spectrum) ----
    for (int n = tid; n < 4096; n += BS)
        Abuf[SW(n)] = make_float2(cr[2*n], cr[2*n + 1]);
    __syncthreads();
    r16_s<-1,0,false>(Abuf, Cbuf, TW); __syncthreads();
    r16_s<-1,1,false>(Cbuf, Abuf, TW); __syncthreads();
    r16_s<-1,2,false>(Abuf, Cbuf, TW); __syncthreads();
    {
        const float sc = 1.0f / 4096.0f;
        for (int k = tid; k <= 2048; k += BS) {
            const int kk = (4096 - k) & 4095;
            float2 t = twl(TW, k << 1);
            float2 W = make_float2(t.x, -t.y);
            float2 Bk, Bkk;
            unpack_pair(Cbuf[SW(k)], Cbuf[SW(kk)], W, Bk, Bkk);
            Fc[k]        = make_float2(Bk.x * sc,  Bk.y * sc);
            Fc[4096 - k] = make_float2(Bkk.x * sc, Bkk.y * sc);
        }
    }
    __syncthreads();

    // ---- Ft = Re(DFT_16384([x, 0, flip(x[1:])])) / 8192 (real half spectrum) ----
    for (int n = tid; n < 8192; n += BS) {
        const int j0 = 2*n, j1 = 2*n + 1;
        float e0 = (j0 < 8192) ? xr[j0] : ((j0 == 8192) ? 0.0f : xr[16384 - j0]);
        float e1 = (j1 < 8192) ? xr[j1] : xr[16384 - j1];
        Abuf[SW(n)] = make_float2(e0, e1);   // fills Abuf+Bbuf region (8192 c)
    }
    __syncthreads();
    r16_round13<-1,0>(Abuf, Cbuf, TW); __syncthreads();
    r16_round13<-1,1>(Cbuf, Abuf, TW); __syncthreads();
    r16_round13<-1,2>(Abuf, Cbuf, TW); __syncthreads();
    r2_full(Cbuf, Abuf);               __syncthreads();
    {
        const float sc = 1.0f / 8192.0f;
        for (int k = tid; k <= 4096; k += BS) {
            const int kk = (8192 - k) & 8191;
            float2 t = twl(TW, k);
            float2 W = make_float2(t.x, -t.y);
            float2 Bk, Bkk;
            unpack_pair(Abuf[SW(k)], Abuf[SW(kk)], W, Bk, Bkk);
            Ft[k]        = Bk.x * sc;
            Ft[8192 - k] = Bkk.x * sc;
        }
    }
    __syncthreads();

    // ---- b = b0 / ||b0||, thread t owns b[16t .. 16t+15] ----
    float b[16];
    {
        #pragma unroll
        for (int q4 = 0; q4 < 4; q4++) {
            const float4 v = *(const float4*)(br + tid*16 + q4*4);
            b[q4*4+0] = v.x; b[q4*4+1] = v.y; b[q4*4+2] = v.z; b[q4*4+3] = v.w;
        }
        float ss = 0.0f;
        #pragma unroll
        for (int i = 0; i < 16; i++) ss += b[i]*b[i];
        float tot = block_reduce_sum(ss, red);
        float inv = 1.0f / sqrtf(tot);
        #pragma unroll
        for (int i = 0; i < 16; i++) b[i] *= inv;
    }

    // ---- 100 power iterations + 1 final application ----
    for (int it = 0; it <= 100; ++it) {
        // pack b into Abuf
        #pragma unroll
        for (int j = 0; j < 8; ++j)
            Abuf[SW(8*tid + j)] = make_float2(b[2*j], b[2*j + 1]);
        __syncthreads();

        // Z = FFT4096(b_packed)  -> Cbuf
        r16_s<-1,0,false>(Abuf, Cbuf, TW); __syncthreads();
        r16_s<-1,1,false>(Cbuf, Abuf, TW); __syncthreads();
        r16_s<-1,2,false>(Abuf, Cbuf, TW); __syncthreads();
        // Z' = specA(Z) in place  (spectrum of u, scaled)
        specA(Cbuf, Fc, TW);               __syncthreads();
        // u = IFFT4096(Z') -> Abuf, Z' preserved in Cbuf
        r16_s<+1,0,false>(Cbuf, Abuf, TW); __syncthreads();
        r16_s<+1,1,false>(Abuf, Bbuf, TW); __syncthreads();
        r16_s<+1,2,false>(Bbuf, Abuf, TW); __syncthreads();
        // Vodd = FFT4096(u_j * exp(-2*pi*i*j/8192)) -> Bbuf
        r16_s<-1,0,true >(Abuf, Bbuf, TW); __syncthreads();
        r16_s<-1,1,false>(Bbuf, Abuf, TW); __syncthreads();
        r16_s<-1,2,false>(Abuf, Bbuf, TW); __syncthreads();
        // specB on both branches in one pass:
        //   even (4096*Z' in Cbuf) -> Dbuf ; odd (Vodd) in-place in Bbuf
        spec_dual(Cbuf, Dbuf, Bbuf, Ft, TW); __syncthreads();
        // dual inverse: E = IFFT4096(even) D->C->D->C ; O = IFFT4096(odd) B->A->B->A
        r16_dual<0>(Dbuf, Cbuf, Bbuf, Abuf, TW); __syncthreads();
        r16_dual<1>(Cbuf, Dbuf, Abuf, Bbuf, TW); __syncthreads();
        r16_dual<2>(Dbuf, Cbuf, Bbuf, Abuf, TW); __syncthreads();
        // combine into registers: w_j = E_j + exp(+2*pi*i*j/8192) * O_j
        float w_[16];
        {
            float sv, cv;
            sincospif((float)(8 * tid) * (1.0f / 4096.0f), &sv, &cv);
            float2 wj = make_float2(cv, sv);
            const float2 CC = make_float2(0.99999970587f, 7.6699031874e-4f); // exp(+i*pi/4096)
            #pragma unroll
            for (int r = 0; r < 8; ++r) {
                const int j = 8 * tid + r;
                float2 E = Cbuf[SW(j)];
                float2 O = Abuf[SW(j)];
                float2 wo = cmul(wj, O);
                w_[2*r]     = E.x + wo.x;
                w_[2*r + 1] = E.y + wo.y;
                wj = cmul(wj, CC);
            }
        }

        if (it < 100) {
            float nb[16];
            float ss = 0.0f;
            #pragma unroll
            for (int i = 0; i < 16; i++) { nb[i] = b[i] - w_[i]; ss += nb[i]*nb[i]; }
            float tot = block_reduce_sum(ss, red);
            float inv = 1.0f / sqrtf(tot);
            int eqp = 1, eqn = 1;
            #pragma unroll
            for (int i = 0; i < 16; i++) {
                float nv = nb[i] * inv;
                eqp &= (nv ==  b[i]);
                eqn &= (nv == -b[i]);
                b[i] = nv;
            }
            eqp = __syncthreads_and(eqp);
            eqn = __syncthreads_and(eqn);
            if (eqp | eqn) it = 99;   // exact fixed point / sign flip: finish
        } else {
            float dp = 0.0f;
            #pragma unroll
            for (int i = 0; i < 16; i++) dp += b[i] * w_[i];
            float tot = block_reduce_sum(dp, red);
            if (tid == 0) g_sigma[row] = 1.0f - tot;   // sigma = b.(b-w)
        }
    }
}

__global__ void finalize_kernel(float* __restrict__ out)
{
    __shared__ float red[16];
    const int t = threadIdx.x;   // 512 threads
    float v = fabsf(g_sigma[t]);
    #pragma unroll
    for (int o = 16; o; o >>= 1) v += __shfl_down_sync(0xffffffffu, v, o);
    if ((t & 31) == 0) red[t >> 5] = v;
    __syncthreads();
    if (t < 16) {
        float s = red[t];
        #pragma unroll
        for (int o = 8; o; o >>= 1) s += __shfl_down_sync(0xffffu, s, o);
        if (t == 0) out[0] = s * (1.0f / 512.0f);
    }
}

extern "C" void kernel_launch(void* const* d_in, const int* in_sizes, int n_in,
                              void* d_out, int out_size)
{
    (void)in_sizes; (void)n_in; (void)out_size;
    const float* x    = (const float*)d_in[0];
    const float* circ = (const float*)d_in[1];
    const float* b0   = (const float*)d_in[2];

    cudaFuncSetAttribute(power_kernel,
                         cudaFuncAttributeMaxDynamicSharedMemorySize, SMEM_BYTES);
    power_kernel<<<NROW, BS, SMEM_BYTES>>>(x, circ, b0);
    finalize_kernel<<<1, 512>>>((float*)d_out);
}